// round 2
// baseline (speedup 1.0000x reference)
#include <cuda_runtime.h>
#include <cstdint>

#define BATCH 4
#define SEQ   2048
#define EMB   1024
#define HEADS 16
#define HDIM  64
#define MTOT  (BATCH*SEQ)   // 8192

// ---------------- scratch (device globals: allocation-free rule) -------------
__device__ float g_q[MTOT*EMB];
__device__ float g_k[MTOT*EMB];
__device__ float g_v[MTOT*EMB];
__device__ float g_ctx[MTOT*EMB];

// ---------------- small PTX helpers -----------------------------------------
__device__ __forceinline__ uint32_t cvt_tf32(float f){
    uint32_t u; asm("cvt.rna.tf32.f32 %0, %1;" : "=r"(u) : "f"(f)); return u;
}
__device__ __forceinline__ void ldsm4(uint32_t a[4], uint32_t saddr){
    asm volatile("ldmatrix.sync.aligned.m8n8.x4.shared.b16 {%0,%1,%2,%3}, [%4];"
        : "=r"(a[0]),"=r"(a[1]),"=r"(a[2]),"=r"(a[3]) : "r"(saddr));
}
__device__ __forceinline__ void mma_tf32(float c[4], const uint32_t a[4],
                                         uint32_t b0, uint32_t b1){
    asm volatile(
        "mma.sync.aligned.m16n8k8.row.col.f32.tf32.tf32.f32 "
        "{%0,%1,%2,%3},{%4,%5,%6,%7},{%8,%9},{%0,%1,%2,%3};"
        : "+f"(c[0]),"+f"(c[1]),"+f"(c[2]),"+f"(c[3])
        : "r"(a[0]),"r"(a[1]),"r"(a[2]),"r"(a[3]),"r"(b0),"r"(b1));
}
__device__ __forceinline__ void cpa16(uint32_t dst, const void* src){
    asm volatile("cp.async.ca.shared.global [%0], [%1], 16;\n" :: "r"(dst), "l"(src));
}
__device__ __forceinline__ void cpa_commit(){ asm volatile("cp.async.commit_group;\n"); }
template<int N> __device__ __forceinline__ void cpa_wait(){
    asm volatile("cp.async.wait_group %0;\n" :: "n"(N));
}

// =============================================================================
// NT GEMM:  out[m,n] = sum_k A[m,k]*W[n,k] + bias[n]
// A: [8192,1024] row-major, W: [1024,1024] row-major (torch Linear weight)
// mode 0: scatter to [B*H, S, 64] (head-split) ; mode 1: flat [M, 1024]
// =============================================================================
#define GBM 128
#define GBN 64
#define GBK 32
#define ASTR 36                      // pad: 36 % 32 == 4  -> conflict-free frags
#define A_STAGE (GBM*ASTR)           // 4608 floats
#define B_STAGE (GBN*ASTR)           // 2304 floats
#define GEMM_SMEM_BYTES ((2*A_STAGE + 2*B_STAGE)*4)   // 55296

__global__ __launch_bounds__(256) void gemm_nt(
    const float* __restrict__ A, const float* __restrict__ W,
    const float* __restrict__ bias, float* __restrict__ out, int mode)
{
    extern __shared__ float sm[];
    float* Bs = sm + 2*A_STAGE;
    const int tid  = threadIdx.x;
    const int lane = tid & 31;
    const int wid  = tid >> 5;
    const int wm   = wid & 3, wn = wid >> 2;
    const int m0 = blockIdx.y * GBM;
    const int n0 = blockIdx.x * GBN;
    const uint32_t sbase = (uint32_t)__cvta_generic_to_shared(sm);

    auto load_stage = [&](int kt, int st){
        const int k0 = kt*GBK;
        const float* ag = A + (size_t)m0*EMB + k0;
        #pragma unroll
        for(int i=0;i<4;i++){
            int idx = tid + i*256;
            int r = idx>>3, c = (idx&7)*4;
            cpa16(sbase + (uint32_t)((st*A_STAGE + r*ASTR + c)*4),
                  ag + (size_t)r*EMB + c);
        }
        const float* wg = W + (size_t)n0*EMB + k0;
        #pragma unroll
        for(int i=0;i<2;i++){
            int idx = tid + i*256;
            int r = idx>>3, c = (idx&7)*4;
            cpa16(sbase + (uint32_t)((2*A_STAGE + st*B_STAGE + r*ASTR + c)*4),
                  wg + (size_t)r*EMB + c);
        }
        cpa_commit();
    };

    float acc[2][4][4] = {};

    load_stage(0, 0);
    const int NKT = EMB/GBK;   // 32
    for(int kt=0; kt<NKT; kt++){
        if(kt+1 < NKT){ load_stage(kt+1, (kt+1)&1); cpa_wait<1>(); }
        else          { cpa_wait<0>(); }
        __syncthreads();
        const int st = kt & 1;

        #pragma unroll
        for(int ks=0; ks<4; ks++){
            uint32_t a[2][4];
            #pragma unroll
            for(int im=0; im<2; im++){
                int r = wm*32 + im*16 + (lane&7) + ((lane>>3)&1)*8;
                int c = ks*8 + (lane>>4)*4;
                ldsm4(a[im], sbase + (uint32_t)((st*A_STAGE + r*ASTR + c)*4));
                #pragma unroll
                for(int t=0;t<4;t++) a[im][t] = cvt_tf32(__uint_as_float(a[im][t]));
            }
            #pragma unroll
            for(int jn=0; jn<4; jn++){
                int nr = wn*32 + jn*8 + (lane>>2);
                int kc = ks*8 + (lane&3);
                float f0 = Bs[st*B_STAGE + nr*ASTR + kc];
                float f1 = Bs[st*B_STAGE + nr*ASTR + kc + 4];
                uint32_t b0 = cvt_tf32(f0), b1 = cvt_tf32(f1);
                mma_tf32(acc[0][jn], a[0], b0, b1);
                mma_tf32(acc[1][jn], a[1], b0, b1);
            }
        }
        __syncthreads();
    }

    // epilogue
    #pragma unroll
    for(int im=0; im<2; im++){
        #pragma unroll
        for(int jn=0; jn<4; jn++){
            int nc = wn*32 + jn*8 + (lane&3)*2;          // col within BN (==HDIM)
            float b0 = bias[n0+nc], b1 = bias[n0+nc+1];
            #pragma unroll
            for(int half=0; half<2; half++){
                int r = m0 + wm*32 + im*16 + (lane>>2) + half*8;
                float v0 = acc[im][jn][half*2+0] + b0;
                float v1 = acc[im][jn][half*2+1] + b1;
                if(mode == 0){
                    int bidx = r >> 11;           // / SEQ
                    int srow = r & (SEQ-1);
                    size_t o = ((size_t)(bidx*HEADS + blockIdx.x)*SEQ + srow)*HDIM + nc;
                    *(float2*)&out[o] = make_float2(v0, v1);
                }else{
                    *(float2*)&out[(size_t)r*EMB + n0 + nc] = make_float2(v0, v1);
                }
            }
        }
    }
}

// =============================================================================
// Flash attention: per block 128 q-rows of one (b,h); loop 32 k-tiles of 64.
// S = Q K^T (tf32 mma), online softmax, P routed via smem, O += P V.
// =============================================================================
#define FBQ 128
#define FBK 64
#define QSTR 68          // 68 % 32 == 4 (ldmatrix + K B-frag conflict-free)
#define KSTR 68
#define VSTR 72          // 72 % 32 == 8 (V B-frag conflict-free)
#define PSTR 68
#define QS_OFF   0
#define QS_SZ    (FBQ*QSTR)                 // 8704
#define KS_OFF   QS_SZ
#define KS_STAGE (FBK*KSTR)                 // 4352
#define VS_OFF   (KS_OFF + 2*KS_STAGE)      // 17408
#define VS_STAGE (FBK*VSTR)                 // 4608
#define PS_OFF   (VS_OFF + 2*VS_STAGE)      // 26624
#define PS_SZ    (FBQ*PSTR)                 // 8704
#define BI_OFF   (PS_OFF + PS_SZ)           // 35328
#define FLASH_SMEM_BYTES ((BI_OFF + 128)*4) // 141824

__global__ __launch_bounds__(256) void flash_attn(
    const float* __restrict__ Qg_, const float* __restrict__ Kg_,
    const float* __restrict__ Vg_, const int* __restrict__ mask,
    float* __restrict__ ctx)
{
    extern __shared__ float sm[];
    const uint32_t sbase = (uint32_t)__cvta_generic_to_shared(sm);
    const int tid = threadIdx.x, lane = tid&31, wid = tid>>5;
    const int bh = blockIdx.y, b = bh>>4, h = bh&15;
    const int q0 = blockIdx.x * FBQ;
    const float* Qg = Qg_ + (size_t)bh*SEQ*HDIM;
    const float* Kg = Kg_ + (size_t)bh*SEQ*HDIM;
    const float* Vg = Vg_ + (size_t)bh*SEQ*HDIM;

    // Q tile (once)
    #pragma unroll
    for(int i=0;i<8;i++){
        int idx = tid + i*256;
        int r = idx>>4, c = (idx&15)*4;
        cpa16(sbase + (uint32_t)((QS_OFF + r*QSTR + c)*4),
              Qg + (size_t)(q0+r)*HDIM + c);
    }
    auto loadKV = [&](int kt, int st){
        const int k0 = kt*FBK;
        #pragma unroll
        for(int i=0;i<4;i++){
            int idx = tid + i*256;
            int r = idx>>4, c = (idx&15)*4;
            cpa16(sbase + (uint32_t)((KS_OFF + st*KS_STAGE + r*KSTR + c)*4),
                  Kg + (size_t)(k0+r)*HDIM + c);
        }
        #pragma unroll
        for(int i=0;i<4;i++){
            int idx = tid + i*256;
            int r = idx>>4, c = (idx&15)*4;
            cpa16(sbase + (uint32_t)((VS_OFF + st*VS_STAGE + r*VSTR + c)*4),
                  Vg + (size_t)(k0+r)*HDIM + c);
        }
        if(tid < FBK){
            int mv = mask[b*SEQ + k0 + tid];
            sm[BI_OFF + st*FBK + tid] = mv ? 0.0f : -1e9f;
        }
        cpa_commit();
    };
    loadKV(0, 0);   // Q + KV0 -> group 0

    float mrow[2] = {-1e30f, -1e30f};
    float lrow[2] = {0.0f, 0.0f};
    float o[8][4] = {};

    const int NT = SEQ/FBK;   // 32
    for(int kt=0; kt<NT; kt++){
        if(kt+1 < NT){ loadKV(kt+1, (kt+1)&1); cpa_wait<1>(); }
        else         { cpa_wait<0>(); }
        __syncthreads();
        const int st = kt & 1;

        // ---- S = Q K^T ----
        float s[8][4] = {};
        #pragma unroll
        for(int kd=0; kd<8; kd++){
            uint32_t a[4];
            {
                int r = wid*16 + (lane&7) + ((lane>>3)&1)*8;
                int c = kd*8 + (lane>>4)*4;
                ldsm4(a, sbase + (uint32_t)((QS_OFF + r*QSTR + c)*4));
                #pragma unroll
                for(int t=0;t<4;t++) a[t] = cvt_tf32(__uint_as_float(a[t]));
            }
            #pragma unroll
            for(int jn=0; jn<8; jn++){
                int nr = jn*8 + (lane>>2);
                int kc = kd*8 + (lane&3);
                float f0 = sm[KS_OFF + st*KS_STAGE + nr*KSTR + kc];
                float f1 = sm[KS_OFF + st*KS_STAGE + nr*KSTR + kc + 4];
                mma_tf32(s[jn], a, cvt_tf32(f0), cvt_tf32(f1));
            }
        }

        // ---- online softmax ----
        float tm0 = -1e30f, tm1 = -1e30f;
        #pragma unroll
        for(int jn=0; jn<8; jn++){
            int col = jn*8 + (lane&3)*2;
            float bb0 = sm[BI_OFF + st*FBK + col];
            float bb1 = sm[BI_OFF + st*FBK + col+1];
            s[jn][0] = s[jn][0]*0.125f + bb0; tm0 = fmaxf(tm0, s[jn][0]);
            s[jn][1] = s[jn][1]*0.125f + bb1; tm0 = fmaxf(tm0, s[jn][1]);
            s[jn][2] = s[jn][2]*0.125f + bb0; tm1 = fmaxf(tm1, s[jn][2]);
            s[jn][3] = s[jn][3]*0.125f + bb1; tm1 = fmaxf(tm1, s[jn][3]);
        }
        tm0 = fmaxf(tm0, __shfl_xor_sync(0xffffffffu, tm0, 1));
        tm0 = fmaxf(tm0, __shfl_xor_sync(0xffffffffu, tm0, 2));
        tm1 = fmaxf(tm1, __shfl_xor_sync(0xffffffffu, tm1, 1));
        tm1 = fmaxf(tm1, __shfl_xor_sync(0xffffffffu, tm1, 2));
        float mn0 = fmaxf(mrow[0], tm0), mn1 = fmaxf(mrow[1], tm1);
        float al0 = __expf(mrow[0]-mn0), al1 = __expf(mrow[1]-mn1);
        mrow[0] = mn0; mrow[1] = mn1;
        float rs0 = 0.0f, rs1 = 0.0f;
        #pragma unroll
        for(int jn=0; jn<8; jn++){
            s[jn][0] = __expf(s[jn][0]-mn0); rs0 += s[jn][0];
            s[jn][1] = __expf(s[jn][1]-mn0); rs0 += s[jn][1];
            s[jn][2] = __expf(s[jn][2]-mn1); rs1 += s[jn][2];
            s[jn][3] = __expf(s[jn][3]-mn1); rs1 += s[jn][3];
        }
        rs0 += __shfl_xor_sync(0xffffffffu, rs0, 1);
        rs0 += __shfl_xor_sync(0xffffffffu, rs0, 2);
        rs1 += __shfl_xor_sync(0xffffffffu, rs1, 1);
        rs1 += __shfl_xor_sync(0xffffffffu, rs1, 2);
        lrow[0] = lrow[0]*al0 + rs0;
        lrow[1] = lrow[1]*al1 + rs1;
        #pragma unroll
        for(int jd=0; jd<8; jd++){
            o[jd][0]*=al0; o[jd][1]*=al0; o[jd][2]*=al1; o[jd][3]*=al1;
        }

        // ---- P -> smem (C-frag layout != A-frag layout for tf32) ----
        {
            int pr0 = wid*16 + (lane>>2);
            #pragma unroll
            for(int jn=0; jn<8; jn++){
                int cc = jn*8 + (lane&3)*2;
                *(float2*)&sm[PS_OFF + pr0*PSTR + cc]     = make_float2(s[jn][0], s[jn][1]);
                *(float2*)&sm[PS_OFF + (pr0+8)*PSTR + cc] = make_float2(s[jn][2], s[jn][3]);
            }
        }
        __syncwarp();

        // ---- O += P V ----
        #pragma unroll
        for(int kk=0; kk<8; kk++){
            uint32_t a[4];
            {
                int r = wid*16 + (lane&7) + ((lane>>3)&1)*8;
                int c = kk*8 + (lane>>4)*4;
                ldsm4(a, sbase + (uint32_t)((PS_OFF + r*PSTR + c)*4));
                #pragma unroll
                for(int t=0;t<4;t++) a[t] = cvt_tf32(__uint_as_float(a[t]));
            }
            #pragma unroll
            for(int jd=0; jd<8; jd++){
                int kr = kk*8 + (lane&3);
                int nc = jd*8 + (lane>>2);
                float f0 = sm[VS_OFF + st*VS_STAGE + kr*VSTR + nc];
                float f1 = sm[VS_OFF + st*VS_STAGE + (kr+4)*VSTR + nc];
                mma_tf32(o[jd], a, cvt_tf32(f0), cvt_tf32(f1));
            }
        }
        __syncthreads();
    }

    // epilogue -> ctx [B,S,E]
    float inv0 = 1.0f/lrow[0], inv1 = 1.0f/lrow[1];
    int gr0 = q0 + wid*16 + (lane>>2);
    #pragma unroll
    for(int jd=0; jd<8; jd++){
        int col = h*HDIM + jd*8 + (lane&3)*2;
        *(float2*)&ctx[(size_t)(b*SEQ + gr0  )*EMB + col] =
            make_float2(o[jd][0]*inv0, o[jd][1]*inv0);
        *(float2*)&ctx[(size_t)(b*SEQ + gr0+8)*EMB + col] =
            make_float2(o[jd][2]*inv1, o[jd][3]*inv1);
    }
}

// =============================================================================
extern "C" void kernel_launch(void* const* d_in, const int* in_sizes, int n_in,
                              void* d_out, int out_size)
{
    const float* x    = (const float*)d_in[0];
    const int*   mask = (const int*)  d_in[1];
    const float* Wq   = (const float*)d_in[2];
    const float* bq   = (const float*)d_in[3];
    const float* Wk   = (const float*)d_in[4];
    const float* bk   = (const float*)d_in[5];
    const float* Wv   = (const float*)d_in[6];
    const float* bv   = (const float*)d_in[7];
    const float* Wo   = (const float*)d_in[8];
    const float* bo   = (const float*)d_in[9];
    float* out = (float*)d_out;

    float *qp, *kp, *vp, *cp;
    cudaGetSymbolAddress((void**)&qp, g_q);
    cudaGetSymbolAddress((void**)&kp, g_k);
    cudaGetSymbolAddress((void**)&vp, g_v);
    cudaGetSymbolAddress((void**)&cp, g_ctx);

    cudaFuncSetAttribute(gemm_nt,   cudaFuncAttributeMaxDynamicSharedMemorySize, GEMM_SMEM_BYTES);
    cudaFuncSetAttribute(flash_attn,cudaFuncAttributeMaxDynamicSharedMemorySize, FLASH_SMEM_BYTES);

    dim3 gg(EMB/GBN, MTOT/GBM);      // (16, 64)
    gemm_nt<<<gg, 256, GEMM_SMEM_BYTES>>>(x, Wq, bq, qp, 0);
    gemm_nt<<<gg, 256, GEMM_SMEM_BYTES>>>(x, Wk, bk, kp, 0);
    gemm_nt<<<gg, 256, GEMM_SMEM_BYTES>>>(x, Wv, bv, vp, 0);

    dim3 fg(SEQ/FBQ, BATCH*HEADS);   // (16, 64)
    flash_attn<<<fg, 256, FLASH_SMEM_BYTES>>>(qp, kp, vp, mask, cp);

    gemm_nt<<<gg, 256, GEMM_SMEM_BYTES>>>(cp, Wo, bo, out, 1);
}

// round 5
// speedup vs baseline: 1.1682x; 1.1682x over previous
#include <cuda_runtime.h>
#include <cstdint>

#define BATCH 4
#define SEQ   2048
#define EMB   1024
#define HEADS 16
#define HDIM  64
#define MTOT  (BATCH*SEQ)   // 8192

// ---------------- scratch (device globals: allocation-free rule) -------------
__device__ float g_q[MTOT*EMB];       // tf32-rounded, pre-scaled by 1/8, head-split
__device__ float g_k[MTOT*EMB];       // tf32-rounded, head-split
__device__ float g_v[MTOT*EMB];       // tf32-rounded, head-split
__device__ float g_ctx[MTOT*EMB];     // tf32-rounded, [B,S,E]
__device__ float g_x[MTOT*EMB];       // tf32-rounded input
__device__ float g_w[4*EMB*EMB];      // tf32-rounded Wq,Wk,Wv,Wo

// ---------------- small PTX helpers -----------------------------------------
__device__ __forceinline__ uint32_t cvt_tf32(float f){
    uint32_t u; asm("cvt.rna.tf32.f32 %0, %1;" : "=r"(u) : "f"(f)); return u;
}
__device__ __forceinline__ void ldsm4(uint32_t a[4], uint32_t saddr){
    asm volatile("ldmatrix.sync.aligned.m8n8.x4.shared.b16 {%0,%1,%2,%3}, [%4];"
        : "=r"(a[0]),"=r"(a[1]),"=r"(a[2]),"=r"(a[3]) : "r"(saddr));
}
__device__ __forceinline__ void mma_tf32(float c[4], const uint32_t a[4],
                                         uint32_t b0, uint32_t b1){
    asm volatile(
        "mma.sync.aligned.m16n8k8.row.col.f32.tf32.tf32.f32 "
        "{%0,%1,%2,%3},{%4,%5,%6,%7},{%8,%9},{%0,%1,%2,%3};"
        : "+f"(c[0]),"+f"(c[1]),"+f"(c[2]),"+f"(c[3])
        : "r"(a[0]),"r"(a[1]),"r"(a[2]),"r"(a[3]),"r"(b0),"r"(b1));
}
__device__ __forceinline__ void cpa16(uint32_t dst, const void* src){
    asm volatile("cp.async.ca.shared.global [%0], [%1], 16;\n" :: "r"(dst), "l"(src));
}
__device__ __forceinline__ void cpa_commit(){ asm volatile("cp.async.commit_group;\n"); }
template<int N> __device__ __forceinline__ void cpa_wait(){
    asm volatile("cp.async.wait_group %0;\n" :: "n"(N));
}

// ---------------- prep: round f32 -> tf32 bit pattern ------------------------
__global__ void round_tf32_k(const float4* __restrict__ src,
                             float4* __restrict__ dst, int n4){
    int i = blockIdx.x*blockDim.x + threadIdx.x;
    if(i < n4){
        float4 v = src[i];
        v.x = __uint_as_float(cvt_tf32(v.x));
        v.y = __uint_as_float(cvt_tf32(v.y));
        v.z = __uint_as_float(cvt_tf32(v.z));
        v.w = __uint_as_float(cvt_tf32(v.w));
        dst[i] = v;
    }
}

// =============================================================================
// NT GEMM:  out[m,n] = (sum_k A[m,k]*W[n,k] + bias[n]) * scale
// A, W pre-rounded to tf32 bits -> no cvt in inner loop.
// mode 0: round + scatter to [B*H, S, 64] ; mode 1: plain flat [M, 1024]
// =============================================================================
#define GBM 128
#define GBN 64
#define GBK 32
#define ASTR 36
#define A_STAGE (GBM*ASTR)
#define B_STAGE (GBN*ASTR)
#define GEMM_SMEM_BYTES ((2*A_STAGE + 2*B_STAGE)*4)   // 55296

__global__ __launch_bounds__(256) void gemm_nt(
    const float* __restrict__ A, const float* __restrict__ W,
    const float* __restrict__ bias, float* __restrict__ out,
    int mode, float scale)
{
    extern __shared__ float sm[];
    float* Bs = sm + 2*A_STAGE;
    const int tid  = threadIdx.x;
    const int lane = tid & 31;
    const int wid  = tid >> 5;
    const int wm   = wid & 3, wn = wid >> 2;
    const int m0 = blockIdx.y * GBM;
    const int n0 = blockIdx.x * GBN;
    const uint32_t sbase = (uint32_t)__cvta_generic_to_shared(sm);

    auto load_stage = [&](int kt, int st){
        const int k0 = kt*GBK;
        const float* ag = A + (size_t)m0*EMB + k0;
        #pragma unroll
        for(int i=0;i<4;i++){
            int idx = tid + i*256;
            int r = idx>>3, c = (idx&7)*4;
            cpa16(sbase + (uint32_t)((st*A_STAGE + r*ASTR + c)*4),
                  ag + (size_t)r*EMB + c);
        }
        const float* wg = W + (size_t)n0*EMB + k0;
        #pragma unroll
        for(int i=0;i<2;i++){
            int idx = tid + i*256;
            int r = idx>>3, c = (idx&7)*4;
            cpa16(sbase + (uint32_t)((2*A_STAGE + st*B_STAGE + r*ASTR + c)*4),
                  wg + (size_t)r*EMB + c);
        }
        cpa_commit();
    };

    float acc[2][4][4] = {};

    load_stage(0, 0);
    const int NKT = EMB/GBK;   // 32
    for(int kt=0; kt<NKT; kt++){
        if(kt+1 < NKT){ load_stage(kt+1, (kt+1)&1); cpa_wait<1>(); }
        else          { cpa_wait<0>(); }
        __syncthreads();
        const int st = kt & 1;

        #pragma unroll
        for(int ks=0; ks<4; ks++){
            uint32_t a[2][4];
            #pragma unroll
            for(int im=0; im<2; im++){
                int r = wm*32 + im*16 + (lane&7) + ((lane>>3)&1)*8;
                int c = ks*8 + (lane>>4)*4;
                ldsm4(a[im], sbase + (uint32_t)((st*A_STAGE + r*ASTR + c)*4));
            }
            #pragma unroll
            for(int jn=0; jn<4; jn++){
                int nr = wn*32 + jn*8 + (lane>>2);
                int kc = ks*8 + (lane&3);
                uint32_t b0 = __float_as_uint(Bs[st*B_STAGE + nr*ASTR + kc]);
                uint32_t b1 = __float_as_uint(Bs[st*B_STAGE + nr*ASTR + kc + 4]);
                mma_tf32(acc[0][jn], a[0], b0, b1);
                mma_tf32(acc[1][jn], a[1], b0, b1);
            }
        }
        __syncthreads();
    }

    // epilogue
    #pragma unroll
    for(int im=0; im<2; im++){
        #pragma unroll
        for(int jn=0; jn<4; jn++){
            int nc = wn*32 + jn*8 + (lane&3)*2;
            float b0 = bias[n0+nc], b1 = bias[n0+nc+1];
            #pragma unroll
            for(int half=0; half<2; half++){
                int r = m0 + wm*32 + im*16 + (lane>>2) + half*8;
                float v0 = acc[im][jn][half*2+0] + b0;
                float v1 = acc[im][jn][half*2+1] + b1;
                if(mode == 0){
                    v0 = __uint_as_float(cvt_tf32(v0*scale));
                    v1 = __uint_as_float(cvt_tf32(v1*scale));
                    int bidx = r >> 11;
                    int srow = r & (SEQ-1);
                    size_t o = ((size_t)(bidx*HEADS + blockIdx.x)*SEQ + srow)*HDIM + nc;
                    *(float2*)&out[o] = make_float2(v0, v1);
                }else{
                    *(float2*)&out[(size_t)r*EMB + n0 + nc] = make_float2(v0, v1);
                }
            }
        }
    }
}

// =============================================================================
// Flash attention v2: 128 threads (4 warps), FBQ=128, M_warp=32.
// Q fragments register-resident; Q smem region reused for P.
// All operands pre-rounded tf32 -> zero cvt in the k-loop.
// smem = 107 KB -> 2 blocks/SM.
// =============================================================================
#define FBQ 128
#define FBK 64
#define KSTR 68
#define VSTR 72
#define PSTR 68
#define KS_OFF   0
#define KS_STAGE (FBK*KSTR)                 // 4352
#define VS_OFF   (2*KS_STAGE)               // 8704
#define VS_STAGE (FBK*VSTR)                 // 4608
#define QP_OFF   (VS_OFF + 2*VS_STAGE)      // 17920
#define QP_SZ    (FBQ*PSTR)                 // 8704
#define BI_OFF   (QP_OFF + QP_SZ)           // 26624
#define FLASH_SMEM_BYTES ((BI_OFF + 128)*4) // 107008

__global__ __launch_bounds__(128, 2) void flash_attn(
    const float* __restrict__ Qg_, const float* __restrict__ Kg_,
    const float* __restrict__ Vg_, const int* __restrict__ mask,
    float* __restrict__ ctx)
{
    extern __shared__ float sm[];
    const uint32_t sbase = (uint32_t)__cvta_generic_to_shared(sm);
    const int tid = threadIdx.x, lane = tid&31, w = tid>>5;
    const int bh = blockIdx.y, b = bh>>4, h = bh&15;
    const int q0 = blockIdx.x * FBQ;
    const float* Qg = Qg_ + (size_t)bh*SEQ*HDIM;
    const float* Kg = Kg_ + (size_t)bh*SEQ*HDIM;
    const float* Vg = Vg_ + (size_t)bh*SEQ*HDIM;

    // Q tile -> smem (group 0)
    #pragma unroll
    for(int i=0;i<16;i++){
        int idx = tid + i*128;
        int r = idx>>4, c = (idx&15)*4;
        cpa16(sbase + (uint32_t)((QP_OFF + r*PSTR + c)*4),
              Qg + (size_t)(q0+r)*HDIM + c);
    }
    cpa_commit();

    auto loadKV = [&](int kt, int st){
        const int k0 = kt*FBK;
        #pragma unroll
        for(int i=0;i<8;i++){
            int idx = tid + i*128;
            int r = idx>>4, c = (idx&15)*4;
            cpa16(sbase + (uint32_t)((KS_OFF + st*KS_STAGE + r*KSTR + c)*4),
                  Kg + (size_t)(k0+r)*HDIM + c);
        }
        #pragma unroll
        for(int i=0;i<8;i++){
            int idx = tid + i*128;
            int r = idx>>4, c = (idx&15)*4;
            cpa16(sbase + (uint32_t)((VS_OFF + st*VS_STAGE + r*VSTR + c)*4),
                  Vg + (size_t)(k0+r)*HDIM + c);
        }
        if(tid < FBK){
            int mv = mask[b*SEQ + k0 + tid];
            sm[BI_OFF + st*FBK + tid] = mv ? 0.0f : -1e9f;
        }
        cpa_commit();
    };
    loadKV(0, 0);    // group 1

    cpa_wait<1>();   // Q ready (only KV0 pending)
    __syncthreads();

    // Q fragments -> registers (warp-exclusive rows; no further sync needed)
    uint32_t qf[8][2][4];
    #pragma unroll
    for(int kd=0; kd<8; kd++){
        #pragma unroll
        for(int im=0; im<2; im++){
            int r = w*32 + im*16 + (lane&7) + ((lane>>3)&1)*8;
            int c = kd*8 + (lane>>4)*4;
            ldsm4(qf[kd][im], sbase + (uint32_t)((QP_OFF + r*PSTR + c)*4));
        }
    }

    float m_[2][2] = {{-1e30f,-1e30f},{-1e30f,-1e30f}};
    float l_[2][2] = {{0.f,0.f},{0.f,0.f}};
    float o[2][8][4] = {};

    const int NT = SEQ/FBK;   // 32
    for(int kt=0; kt<NT; kt++){
        if(kt+1 < NT){ loadKV(kt+1, (kt+1)&1); cpa_wait<1>(); }
        else         { cpa_wait<0>(); }
        __syncthreads();
        const int st = kt & 1;

        // ---- S = Q K^T (Q pre-scaled by 1/8) ----
        float s[2][8][4] = {};
        #pragma unroll
        for(int kd=0; kd<8; kd++){
            #pragma unroll
            for(int jn=0; jn<8; jn++){
                int nr = jn*8 + (lane>>2);
                int kc = kd*8 + (lane&3);
                uint32_t b0 = __float_as_uint(sm[KS_OFF + st*KS_STAGE + nr*KSTR + kc]);
                uint32_t b1 = __float_as_uint(sm[KS_OFF + st*KS_STAGE + nr*KSTR + kc + 4]);
                mma_tf32(s[0][jn], qf[kd][0], b0, b1);
                mma_tf32(s[1][jn], qf[kd][1], b0, b1);
            }
        }

        // ---- online softmax ----
        #pragma unroll
        for(int im=0; im<2; im++){
            float tm0 = -1e30f, tm1 = -1e30f;
            #pragma unroll
            for(int jn=0; jn<8; jn++){
                int col = jn*8 + (lane&3)*2;
                float bb0 = sm[BI_OFF + st*FBK + col];
                float bb1 = sm[BI_OFF + st*FBK + col+1];
                s[im][jn][0] += bb0; tm0 = fmaxf(tm0, s[im][jn][0]);
                s[im][jn][1] += bb1; tm0 = fmaxf(tm0, s[im][jn][1]);
                s[im][jn][2] += bb0; tm1 = fmaxf(tm1, s[im][jn][2]);
                s[im][jn][3] += bb1; tm1 = fmaxf(tm1, s[im][jn][3]);
            }
            tm0 = fmaxf(tm0, __shfl_xor_sync(0xffffffffu, tm0, 1));
            tm0 = fmaxf(tm0, __shfl_xor_sync(0xffffffffu, tm0, 2));
            tm1 = fmaxf(tm1, __shfl_xor_sync(0xffffffffu, tm1, 1));
            tm1 = fmaxf(tm1, __shfl_xor_sync(0xffffffffu, tm1, 2));
            float mn0 = fmaxf(m_[im][0], tm0), mn1 = fmaxf(m_[im][1], tm1);
            float al0 = __expf(m_[im][0]-mn0), al1 = __expf(m_[im][1]-mn1);
            m_[im][0] = mn0; m_[im][1] = mn1;
            float rs0 = 0.f, rs1 = 0.f;
            #pragma unroll
            for(int jn=0; jn<8; jn++){
                s[im][jn][0] = __expf(s[im][jn][0]-mn0); rs0 += s[im][jn][0];
                s[im][jn][1] = __expf(s[im][jn][1]-mn0); rs0 += s[im][jn][1];
                s[im][jn][2] = __expf(s[im][jn][2]-mn1); rs1 += s[im][jn][2];
                s[im][jn][3] = __expf(s[im][jn][3]-mn1); rs1 += s[im][jn][3];
            }
            rs0 += __shfl_xor_sync(0xffffffffu, rs0, 1);
            rs0 += __shfl_xor_sync(0xffffffffu, rs0, 2);
            rs1 += __shfl_xor_sync(0xffffffffu, rs1, 1);
            rs1 += __shfl_xor_sync(0xffffffffu, rs1, 2);
            l_[im][0] = l_[im][0]*al0 + rs0;
            l_[im][1] = l_[im][1]*al1 + rs1;
            #pragma unroll
            for(int jd=0; jd<8; jd++){
                o[im][jd][0]*=al0; o[im][jd][1]*=al0;
                o[im][jd][2]*=al1; o[im][jd][3]*=al1;
            }
        }

        // ---- P (rounded) -> smem, reusing Q region (warp-exclusive rows) ----
        #pragma unroll
        for(int im=0; im<2; im++){
            int pr = w*32 + im*16 + (lane>>2);
            #pragma unroll
            for(int jn=0; jn<8; jn++){
                int cc = jn*8 + (lane&3)*2;
                *(float2*)&sm[QP_OFF + pr*PSTR + cc] = make_float2(
                    __uint_as_float(cvt_tf32(s[im][jn][0])),
                    __uint_as_float(cvt_tf32(s[im][jn][1])));
                *(float2*)&sm[QP_OFF + (pr+8)*PSTR + cc] = make_float2(
                    __uint_as_float(cvt_tf32(s[im][jn][2])),
                    __uint_as_float(cvt_tf32(s[im][jn][3])));
            }
        }
        __syncwarp();

        // ---- O += P V ----
        #pragma unroll
        for(int kk=0; kk<8; kk++){
            uint32_t pf[2][4];
            #pragma unroll
            for(int im=0; im<2; im++){
                int r = w*32 + im*16 + (lane&7) + ((lane>>3)&1)*8;
                int c = kk*8 + (lane>>4)*4;
                ldsm4(pf[im], sbase + (uint32_t)((QP_OFF + r*PSTR + c)*4));
            }
            #pragma unroll
            for(int jd=0; jd<8; jd++){
                int kr = kk*8 + (lane&3);
                int nc = jd*8 + (lane>>2);
                uint32_t b0 = __float_as_uint(sm[VS_OFF + st*VS_STAGE + kr*VSTR + nc]);
                uint32_t b1 = __float_as_uint(sm[VS_OFF + st*VS_STAGE + (kr+4)*VSTR + nc]);
                mma_tf32(o[0][jd], pf[0], b0, b1);
                mma_tf32(o[1][jd], pf[1], b0, b1);
            }
        }
        __syncthreads();
    }

    // epilogue -> ctx [B,S,E], rounded for the output GEMM
    #pragma unroll
    for(int im=0; im<2; im++){
        float inv0 = 1.0f/l_[im][0], inv1 = 1.0f/l_[im][1];
        int gr0 = q0 + w*32 + im*16 + (lane>>2);
        #pragma unroll
        for(int jd=0; jd<8; jd++){
            int col = h*HDIM + jd*8 + (lane&3)*2;
            *(float2*)&ctx[(size_t)(b*SEQ + gr0  )*EMB + col] = make_float2(
                __uint_as_float(cvt_tf32(o[im][jd][0]*inv0)),
                __uint_as_float(cvt_tf32(o[im][jd][1]*inv0)));
            *(float2*)&ctx[(size_t)(b*SEQ + gr0+8)*EMB + col] = make_float2(
                __uint_as_float(cvt_tf32(o[im][jd][2]*inv1)),
                __uint_as_float(cvt_tf32(o[im][jd][3]*inv1)));
        }
    }
}

// =============================================================================
extern "C" void kernel_launch(void* const* d_in, const int* in_sizes, int n_in,
                              void* d_out, int out_size)
{
    const float* x    = (const float*)d_in[0];
    const int*   mask = (const int*)  d_in[1];
    const float* Wq   = (const float*)d_in[2];
    const float* bq   = (const float*)d_in[3];
    const float* Wk   = (const float*)d_in[4];
    const float* bk   = (const float*)d_in[5];
    const float* Wv   = (const float*)d_in[6];
    const float* bv   = (const float*)d_in[7];
    const float* Wo   = (const float*)d_in[8];
    const float* bo   = (const float*)d_in[9];
    float* out = (float*)d_out;

    float *qp, *kp, *vp, *cp, *xp, *wp;
    cudaGetSymbolAddress((void**)&qp, g_q);
    cudaGetSymbolAddress((void**)&kp, g_k);
    cudaGetSymbolAddress((void**)&vp, g_v);
    cudaGetSymbolAddress((void**)&cp, g_ctx);
    cudaGetSymbolAddress((void**)&xp, g_x);
    cudaGetSymbolAddress((void**)&wp, g_w);

    cudaFuncSetAttribute(gemm_nt,   cudaFuncAttributeMaxDynamicSharedMemorySize, GEMM_SMEM_BYTES);
    cudaFuncSetAttribute(flash_attn,cudaFuncAttributeMaxDynamicSharedMemorySize, FLASH_SMEM_BYTES);

    // prep: tf32-round inputs/weights once per launch
    {
        int n4x = MTOT*EMB/4, n4w = EMB*EMB/4;
        round_tf32_k<<<(n4x+255)/256, 256>>>((const float4*)x,  (float4*)xp, n4x);
        round_tf32_k<<<(n4w+255)/256, 256>>>((const float4*)Wq, (float4*)(wp        ), n4w);
        round_tf32_k<<<(n4w+255)/256, 256>>>((const float4*)Wk, (float4*)(wp+  EMB*EMB), n4w);
        round_tf32_k<<<(n4w+255)/256, 256>>>((const float4*)Wv, (float4*)(wp+2*EMB*EMB), n4w);
        round_tf32_k<<<(n4w+255)/256, 256>>>((const float4*)Wo, (float4*)(wp+3*EMB*EMB), n4w);
    }

    dim3 gg(EMB/GBN, MTOT/GBM);      // (16, 64)
    gemm_nt<<<gg, 256, GEMM_SMEM_BYTES>>>(xp, wp,           bq, qp, 0, 0.125f);
    gemm_nt<<<gg, 256, GEMM_SMEM_BYTES>>>(xp, wp+  EMB*EMB, bk, kp, 0, 1.0f);
    gemm_nt<<<gg, 256, GEMM_SMEM_BYTES>>>(xp, wp+2*EMB*EMB, bv, vp, 0, 1.0f);

    dim3 fg(SEQ/FBQ, BATCH*HEADS);   // (16, 64)
    flash_attn<<<fg, 128, FLASH_SMEM_BYTES>>>(qp, kp, vp, mask, cp);

    gemm_nt<<<gg, 256, GEMM_SMEM_BYTES>>>(cp, wp+3*EMB*EMB, bo, out, 1, 1.0f);
}

// round 6
// speedup vs baseline: 1.1985x; 1.0259x over previous
#include <cuda_runtime.h>
#include <cstdint>

#define BATCH 4
#define SEQ   2048
#define EMB   1024
#define HEADS 16
#define HDIM  64
#define MTOT  (BATCH*SEQ)   // 8192

// ---------------- scratch (device globals: allocation-free rule) -------------
__device__ float g_q[MTOT*EMB];       // tf32-rounded, pre-scaled by 1/8, head-split
__device__ float g_k[MTOT*EMB];       // tf32-rounded, head-split
__device__ float g_v[MTOT*EMB];       // tf32-rounded, head-split
__device__ float g_ctx[MTOT*EMB];     // tf32-rounded, [B,S,E]
__device__ float g_x[MTOT*EMB];       // tf32-rounded input
__device__ float g_w[4*EMB*EMB];      // tf32-rounded Wq,Wk,Wv,Wo (contiguous)
__device__ float g_b[3*EMB];          // packed bq|bk|bv

// ---------------- small PTX helpers -----------------------------------------
__device__ __forceinline__ uint32_t cvt_tf32(float f){
    uint32_t u; asm("cvt.rna.tf32.f32 %0, %1;" : "=r"(u) : "f"(f)); return u;
}
__device__ __forceinline__ void ldsm4(uint32_t a[4], uint32_t saddr){
    asm volatile("ldmatrix.sync.aligned.m8n8.x4.shared.b16 {%0,%1,%2,%3}, [%4];"
        : "=r"(a[0]),"=r"(a[1]),"=r"(a[2]),"=r"(a[3]) : "r"(saddr));
}
__device__ __forceinline__ void mma_tf32(float c[4], const uint32_t a[4],
                                         uint32_t b0, uint32_t b1){
    asm volatile(
        "mma.sync.aligned.m16n8k8.row.col.f32.tf32.tf32.f32 "
        "{%0,%1,%2,%3},{%4,%5,%6,%7},{%8,%9},{%0,%1,%2,%3};"
        : "+f"(c[0]),"+f"(c[1]),"+f"(c[2]),"+f"(c[3])
        : "r"(a[0]),"r"(a[1]),"r"(a[2]),"r"(a[3]),"r"(b0),"r"(b1));
}
__device__ __forceinline__ void cpa16(uint32_t dst, const void* src){
    asm volatile("cp.async.ca.shared.global [%0], [%1], 16;\n" :: "r"(dst), "l"(src));
}
__device__ __forceinline__ void cpa_commit(){ asm volatile("cp.async.commit_group;\n"); }
template<int N> __device__ __forceinline__ void cpa_wait(){
    asm volatile("cp.async.wait_group %0;\n" :: "n"(N));
}

// ---------------- fused prep: round x + 4 W, pack biases ---------------------
#define N4X (MTOT*EMB/4)     // 2097152
#define N4W (EMB*EMB/4)      // 262144
__device__ __forceinline__ float4 round4(float4 v){
    v.x = __uint_as_float(cvt_tf32(v.x));
    v.y = __uint_as_float(cvt_tf32(v.y));
    v.z = __uint_as_float(cvt_tf32(v.z));
    v.w = __uint_as_float(cvt_tf32(v.w));
    return v;
}
__global__ void prep_k(
    const float4* __restrict__ x,
    const float4* __restrict__ Wq, const float4* __restrict__ Wk,
    const float4* __restrict__ Wv, const float4* __restrict__ Wo,
    const float*  __restrict__ bq, const float* __restrict__ bk,
    const float*  __restrict__ bv,
    float4* __restrict__ xp, float4* __restrict__ wp, float* __restrict__ bp)
{
    int i = blockIdx.x*blockDim.x + threadIdx.x;
    if(i < N4X){
        xp[i] = round4(x[i]);
    } else if(i < N4X + 4*N4W){
        int j = i - N4X;
        int w = j >> 18;           // /N4W (2^18)
        int off = j & (N4W-1);
        const float4* src = (w==0)?Wq : (w==1)?Wk : (w==2)?Wv : Wo;
        wp[(size_t)w*N4W + off] = round4(src[off]);
    } else {
        int j = i - (N4X + 4*N4W);
        if(j < 3*EMB){
            int seg = j >> 10, off = j & (EMB-1);
            const float* src = (seg==0)?bq : (seg==1)?bk : bv;
            bp[j] = src[off];
        }
    }
}
#define PREP_TOTAL (N4X + 4*N4W + 3*EMB)

// =============================================================================
// NT GEMM, 3-stage cp.async pipeline, one __syncthreads per k-iter.
//   out[m,n] = sum_k A[m,k]*W[n,k] + bias[n]
// fused=1: N=3072 (Wq|Wk|Wv); seg=blockIdx.x>>4 selects dest + scale(Q:1/8);
//          round + scatter to [B*H, S, 64].
// fused=0: N=1024 flat [M,1024] store (output projection).
// =============================================================================
#define GBM 128
#define GBN 64
#define GBK 32
#define ASTR 36
#define A_STAGE (GBM*ASTR)               // 4608 floats
#define B_STAGE (GBN*ASTR)               // 2304 floats
#define STG_SZ  (A_STAGE + B_STAGE)      // 6912 floats
#define GEMM_SMEM_BYTES (3*STG_SZ*4)     // 82944

__global__ __launch_bounds__(256) void gemm_nt(
    const float* __restrict__ A, const float* __restrict__ W,
    const float* __restrict__ bias,
    float* __restrict__ oQ, float* __restrict__ oK, float* __restrict__ oV,
    int fused)
{
    extern __shared__ float sm[];
    const int tid  = threadIdx.x;
    const int lane = tid & 31;
    const int wid  = tid >> 5;
    const int wm   = wid & 3, wn = wid >> 2;
    const int m0 = blockIdx.y * GBM;
    const int n0 = blockIdx.x * GBN;
    const uint32_t sbase = (uint32_t)__cvta_generic_to_shared(sm);

    auto load_stage = [&](int kt, int st){
        const int k0 = kt*GBK;
        const int base = st*STG_SZ;
        const float* ag = A + (size_t)m0*EMB + k0;
        #pragma unroll
        for(int i=0;i<4;i++){
            int idx = tid + i*256;
            int r = idx>>3, c = (idx&7)*4;
            cpa16(sbase + (uint32_t)((base + r*ASTR + c)*4),
                  ag + (size_t)r*EMB + c);
        }
        const float* wg = W + (size_t)n0*EMB + k0;
        #pragma unroll
        for(int i=0;i<2;i++){
            int idx = tid + i*256;
            int r = idx>>3, c = (idx&7)*4;
            cpa16(sbase + (uint32_t)((base + A_STAGE + r*ASTR + c)*4),
                  wg + (size_t)r*EMB + c);
        }
        cpa_commit();
    };

    float acc[2][4][4] = {};

    load_stage(0, 0);
    load_stage(1, 1);
    const int NKT = EMB/GBK;   // 32
    for(int kt=0; kt<NKT; kt++){
        if(kt == NKT-1) cpa_wait<0>(); else cpa_wait<1>();
        __syncthreads();
        const int st = kt % 3;
        const int base = st*STG_SZ;
        const float* Bs = sm + base + A_STAGE;

        #pragma unroll
        for(int ks=0; ks<4; ks++){
            uint32_t a[2][4];
            #pragma unroll
            for(int im=0; im<2; im++){
                int r = wm*32 + im*16 + (lane&7) + ((lane>>3)&1)*8;
                int c = ks*8 + (lane>>4)*4;
                ldsm4(a[im], sbase + (uint32_t)((base + r*ASTR + c)*4));
            }
            #pragma unroll
            for(int jn=0; jn<4; jn++){
                int nr = wn*32 + jn*8 + (lane>>2);
                int kc = ks*8 + (lane&3);
                uint32_t b0 = __float_as_uint(Bs[nr*ASTR + kc]);
                uint32_t b1 = __float_as_uint(Bs[nr*ASTR + kc + 4]);
                mma_tf32(acc[0][jn], a[0], b0, b1);
                mma_tf32(acc[1][jn], a[1], b0, b1);
            }
        }
        if(kt+2 < NKT) load_stage(kt+2, (kt+2)%3);
    }

    // epilogue
    float scale = 1.0f;
    float* outp = oQ;
    int head = blockIdx.x;
    if(fused){
        int seg = blockIdx.x >> 4;
        head = blockIdx.x & 15;
        outp = (seg==0) ? oQ : (seg==1) ? oK : oV;
        scale = (seg==0) ? 0.125f : 1.0f;
    }
    #pragma unroll
    for(int im=0; im<2; im++){
        #pragma unroll
        for(int jn=0; jn<4; jn++){
            int nc = wn*32 + jn*8 + (lane&3)*2;
            float b0 = bias[n0+nc], b1 = bias[n0+nc+1];
            #pragma unroll
            for(int half=0; half<2; half++){
                int r = m0 + wm*32 + im*16 + (lane>>2) + half*8;
                float v0 = acc[im][jn][half*2+0] + b0;
                float v1 = acc[im][jn][half*2+1] + b1;
                if(fused){
                    v0 = __uint_as_float(cvt_tf32(v0*scale));
                    v1 = __uint_as_float(cvt_tf32(v1*scale));
                    int bidx = r >> 11;
                    int srow = r & (SEQ-1);
                    size_t o = ((size_t)(bidx*HEADS + head)*SEQ + srow)*HDIM + nc;
                    *(float2*)&outp[o] = make_float2(v0, v1);
                }else{
                    *(float2*)&outp[(size_t)r*EMB + n0 + nc] = make_float2(v0, v1);
                }
            }
        }
    }
}

// =============================================================================
// Flash attention: 128 threads (4 warps), FBQ=128, M_warp=32.
// Q fragments register-resident; Q smem region reused for P.
// All operands pre-rounded tf32 -> zero cvt in the k-loop. 2 blocks/SM.
// =============================================================================
#define FBQ 128
#define FBK 64
#define KSTR 68
#define VSTR 72
#define PSTR 68
#define KS_OFF   0
#define KS_STAGE (FBK*KSTR)                 // 4352
#define VS_OFF   (2*KS_STAGE)               // 8704
#define VS_STAGE (FBK*VSTR)                 // 4608
#define QP_OFF   (VS_OFF + 2*VS_STAGE)      // 17920
#define QP_SZ    (FBQ*PSTR)                 // 8704
#define BI_OFF   (QP_OFF + QP_SZ)           // 26624
#define FLASH_SMEM_BYTES ((BI_OFF + 128)*4) // 107008

__global__ __launch_bounds__(128, 2) void flash_attn(
    const float* __restrict__ Qg_, const float* __restrict__ Kg_,
    const float* __restrict__ Vg_, const int* __restrict__ mask,
    float* __restrict__ ctx)
{
    extern __shared__ float sm[];
    const uint32_t sbase = (uint32_t)__cvta_generic_to_shared(sm);
    const int tid = threadIdx.x, lane = tid&31, w = tid>>5;
    const int bh = blockIdx.y, b = bh>>4, h = bh&15;
    const int q0 = blockIdx.x * FBQ;
    const float* Qg = Qg_ + (size_t)bh*SEQ*HDIM;
    const float* Kg = Kg_ + (size_t)bh*SEQ*HDIM;
    const float* Vg = Vg_ + (size_t)bh*SEQ*HDIM;

    // Q tile -> smem (group 0)
    #pragma unroll
    for(int i=0;i<16;i++){
        int idx = tid + i*128;
        int r = idx>>4, c = (idx&15)*4;
        cpa16(sbase + (uint32_t)((QP_OFF + r*PSTR + c)*4),
              Qg + (size_t)(q0+r)*HDIM + c);
    }
    cpa_commit();

    auto loadKV = [&](int kt, int st){
        const int k0 = kt*FBK;
        #pragma unroll
        for(int i=0;i<8;i++){
            int idx = tid + i*128;
            int r = idx>>4, c = (idx&15)*4;
            cpa16(sbase + (uint32_t)((KS_OFF + st*KS_STAGE + r*KSTR + c)*4),
                  Kg + (size_t)(k0+r)*HDIM + c);
        }
        #pragma unroll
        for(int i=0;i<8;i++){
            int idx = tid + i*128;
            int r = idx>>4, c = (idx&15)*4;
            cpa16(sbase + (uint32_t)((VS_OFF + st*VS_STAGE + r*VSTR + c)*4),
                  Vg + (size_t)(k0+r)*HDIM + c);
        }
        if(tid < FBK){
            int mv = mask[b*SEQ + k0 + tid];
            sm[BI_OFF + st*FBK + tid] = mv ? 0.0f : -1e9f;
        }
        cpa_commit();
    };
    loadKV(0, 0);    // group 1

    cpa_wait<1>();   // Q ready (only KV0 pending)
    __syncthreads();

    // Q fragments -> registers (warp-exclusive rows)
    uint32_t qf[8][2][4];
    #pragma unroll
    for(int kd=0; kd<8; kd++){
        #pragma unroll
        for(int im=0; im<2; im++){
            int r = w*32 + im*16 + (lane&7) + ((lane>>3)&1)*8;
            int c = kd*8 + (lane>>4)*4;
            ldsm4(qf[kd][im], sbase + (uint32_t)((QP_OFF + r*PSTR + c)*4));
        }
    }

    float m_[2][2] = {{-1e30f,-1e30f},{-1e30f,-1e30f}};
    float l_[2][2] = {{0.f,0.f},{0.f,0.f}};
    float o[2][8][4] = {};

    const int NT = SEQ/FBK;   // 32
    for(int kt=0; kt<NT; kt++){
        if(kt+1 < NT){ loadKV(kt+1, (kt+1)&1); cpa_wait<1>(); }
        else         { cpa_wait<0>(); }
        __syncthreads();
        const int st = kt & 1;

        // ---- S = Q K^T (Q pre-scaled by 1/8) ----
        float s[2][8][4] = {};
        #pragma unroll
        for(int kd=0; kd<8; kd++){
            #pragma unroll
            for(int jn=0; jn<8; jn++){
                int nr = jn*8 + (lane>>2);
                int kc = kd*8 + (lane&3);
                uint32_t b0 = __float_as_uint(sm[KS_OFF + st*KS_STAGE + nr*KSTR + kc]);
                uint32_t b1 = __float_as_uint(sm[KS_OFF + st*KS_STAGE + nr*KSTR + kc + 4]);
                mma_tf32(s[0][jn], qf[kd][0], b0, b1);
                mma_tf32(s[1][jn], qf[kd][1], b0, b1);
            }
        }

        // ---- online softmax ----
        #pragma unroll
        for(int im=0; im<2; im++){
            float tm0 = -1e30f, tm1 = -1e30f;
            #pragma unroll
            for(int jn=0; jn<8; jn++){
                int col = jn*8 + (lane&3)*2;
                float bb0 = sm[BI_OFF + st*FBK + col];
                float bb1 = sm[BI_OFF + st*FBK + col+1];
                s[im][jn][0] += bb0; tm0 = fmaxf(tm0, s[im][jn][0]);
                s[im][jn][1] += bb1; tm0 = fmaxf(tm0, s[im][jn][1]);
                s[im][jn][2] += bb0; tm1 = fmaxf(tm1, s[im][jn][2]);
                s[im][jn][3] += bb1; tm1 = fmaxf(tm1, s[im][jn][3]);
            }
            tm0 = fmaxf(tm0, __shfl_xor_sync(0xffffffffu, tm0, 1));
            tm0 = fmaxf(tm0, __shfl_xor_sync(0xffffffffu, tm0, 2));
            tm1 = fmaxf(tm1, __shfl_xor_sync(0xffffffffu, tm1, 1));
            tm1 = fmaxf(tm1, __shfl_xor_sync(0xffffffffu, tm1, 2));
            float mn0 = fmaxf(m_[im][0], tm0), mn1 = fmaxf(m_[im][1], tm1);
            float al0 = __expf(m_[im][0]-mn0), al1 = __expf(m_[im][1]-mn1);
            m_[im][0] = mn0; m_[im][1] = mn1;
            float rs0 = 0.f, rs1 = 0.f;
            #pragma unroll
            for(int jn=0; jn<8; jn++){
                s[im][jn][0] = __expf(s[im][jn][0]-mn0); rs0 += s[im][jn][0];
                s[im][jn][1] = __expf(s[im][jn][1]-mn0); rs0 += s[im][jn][1];
                s[im][jn][2] = __expf(s[im][jn][2]-mn1); rs1 += s[im][jn][2];
                s[im][jn][3] = __expf(s[im][jn][3]-mn1); rs1 += s[im][jn][3];
            }
            rs0 += __shfl_xor_sync(0xffffffffu, rs0, 1);
            rs0 += __shfl_xor_sync(0xffffffffu, rs0, 2);
            rs1 += __shfl_xor_sync(0xffffffffu, rs1, 1);
            rs1 += __shfl_xor_sync(0xffffffffu, rs1, 2);
            l_[im][0] = l_[im][0]*al0 + rs0;
            l_[im][1] = l_[im][1]*al1 + rs1;
            #pragma unroll
            for(int jd=0; jd<8; jd++){
                o[im][jd][0]*=al0; o[im][jd][1]*=al0;
                o[im][jd][2]*=al1; o[im][jd][3]*=al1;
            }
        }

        // ---- P (rounded) -> smem, reusing Q region (warp-exclusive rows) ----
        #pragma unroll
        for(int im=0; im<2; im++){
            int pr = w*32 + im*16 + (lane>>2);
            #pragma unroll
            for(int jn=0; jn<8; jn++){
                int cc = jn*8 + (lane&3)*2;
                *(float2*)&sm[QP_OFF + pr*PSTR + cc] = make_float2(
                    __uint_as_float(cvt_tf32(s[im][jn][0])),
                    __uint_as_float(cvt_tf32(s[im][jn][1])));
                *(float2*)&sm[QP_OFF + (pr+8)*PSTR + cc] = make_float2(
                    __uint_as_float(cvt_tf32(s[im][jn][2])),
                    __uint_as_float(cvt_tf32(s[im][jn][3])));
            }
        }
        __syncwarp();

        // ---- O += P V ----
        #pragma unroll
        for(int kk=0; kk<8; kk++){
            uint32_t pf[2][4];
            #pragma unroll
            for(int im=0; im<2; im++){
                int r = w*32 + im*16 + (lane&7) + ((lane>>3)&1)*8;
                int c = kk*8 + (lane>>4)*4;
                ldsm4(pf[im], sbase + (uint32_t)((QP_OFF + r*PSTR + c)*4));
            }
            #pragma unroll
            for(int jd=0; jd<8; jd++){
                int kr = kk*8 + (lane&3);
                int nc = jd*8 + (lane>>2);
                uint32_t b0 = __float_as_uint(sm[VS_OFF + st*VS_STAGE + kr*VSTR + nc]);
                uint32_t b1 = __float_as_uint(sm[VS_OFF + st*VS_STAGE + (kr+4)*VSTR + nc]);
                mma_tf32(o[0][jd], pf[0], b0, b1);
                mma_tf32(o[1][jd], pf[1], b0, b1);
            }
        }
        __syncthreads();
    }

    // epilogue -> ctx [B,S,E], rounded for the output GEMM
    #pragma unroll
    for(int im=0; im<2; im++){
        float inv0 = 1.0f/l_[im][0], inv1 = 1.0f/l_[im][1];
        int gr0 = q0 + w*32 + im*16 + (lane>>2);
        #pragma unroll
        for(int jd=0; jd<8; jd++){
            int col = h*HDIM + jd*8 + (lane&3)*2;
            *(float2*)&ctx[(size_t)(b*SEQ + gr0  )*EMB + col] = make_float2(
                __uint_as_float(cvt_tf32(o[im][jd][0]*inv0)),
                __uint_as_float(cvt_tf32(o[im][jd][1]*inv0)));
            *(float2*)&ctx[(size_t)(b*SEQ + gr0+8)*EMB + col] = make_float2(
                __uint_as_float(cvt_tf32(o[im][jd][2]*inv1)),
                __uint_as_float(cvt_tf32(o[im][jd][3]*inv1)));
        }
    }
}

// =============================================================================
extern "C" void kernel_launch(void* const* d_in, const int* in_sizes, int n_in,
                              void* d_out, int out_size)
{
    const float* x    = (const float*)d_in[0];
    const int*   mask = (const int*)  d_in[1];
    const float* Wq   = (const float*)d_in[2];
    const float* bq   = (const float*)d_in[3];
    const float* Wk   = (const float*)d_in[4];
    const float* bk   = (const float*)d_in[5];
    const float* Wv   = (const float*)d_in[6];
    const float* bv   = (const float*)d_in[7];
    const float* Wo   = (const float*)d_in[8];
    const float* bo   = (const float*)d_in[9];
    float* out = (float*)d_out;

    float *qp, *kp, *vp, *cp, *xp, *wp, *bp;
    cudaGetSymbolAddress((void**)&qp, g_q);
    cudaGetSymbolAddress((void**)&kp, g_k);
    cudaGetSymbolAddress((void**)&vp, g_v);
    cudaGetSymbolAddress((void**)&cp, g_ctx);
    cudaGetSymbolAddress((void**)&xp, g_x);
    cudaGetSymbolAddress((void**)&wp, g_w);
    cudaGetSymbolAddress((void**)&bp, g_b);

    cudaFuncSetAttribute(gemm_nt,   cudaFuncAttributeMaxDynamicSharedMemorySize, GEMM_SMEM_BYTES);
    cudaFuncSetAttribute(flash_attn,cudaFuncAttributeMaxDynamicSharedMemorySize, FLASH_SMEM_BYTES);

    // 1) fused prep (single launch)
    prep_k<<<(PREP_TOTAL+255)/256, 256>>>(
        (const float4*)x, (const float4*)Wq, (const float4*)Wk,
        (const float4*)Wv, (const float4*)Wo,
        bq, bk, bv,
        (float4*)xp, (float4*)wp, bp);

    // 2) fused QKV projection (N=3072)
    dim3 gqkv(3*EMB/GBN, MTOT/GBM);  // (48, 64)
    gemm_nt<<<gqkv, 256, GEMM_SMEM_BYTES>>>(xp, wp, bp, qp, kp, vp, 1);

    // 3) flash attention
    dim3 fg(SEQ/FBQ, BATCH*HEADS);   // (16, 64)
    flash_attn<<<fg, 128, FLASH_SMEM_BYTES>>>(qp, kp, vp, mask, cp);

    // 4) output projection
    dim3 go(EMB/GBN, MTOT/GBM);      // (16, 64)
    gemm_nt<<<go, 256, GEMM_SMEM_BYTES>>>(cp, wp+3*(size_t)EMB*EMB, bo, out, nullptr, nullptr, 0);
}

// round 7
// speedup vs baseline: 1.2382x; 1.0331x over previous
#include <cuda_runtime.h>
#include <cstdint>

#define BATCH 4
#define SEQ   2048
#define EMB   1024
#define HEADS 16
#define HDIM  64
#define MTOT  (BATCH*SEQ)   // 8192

// ---------------- scratch (device globals: allocation-free rule) -------------
__device__ float g_q[MTOT*EMB];       // tf32-rounded, pre-scaled 1/8, [bh][s][d]
__device__ float g_k[MTOT*EMB];       // tf32-rounded, [bh][s][d]
__device__ float g_v[MTOT*EMB];       // tf32-rounded, TRANSPOSED [bh][d][s]
__device__ float g_ctx[MTOT*EMB];     // tf32-rounded, [B,S,E]
__device__ float g_x[MTOT*EMB];       // tf32-rounded input
__device__ float g_w[4*EMB*EMB];      // tf32-rounded Wq,Wk,Wv,Wo (contiguous)
__device__ float g_b[3*EMB];          // packed bq|bk|bv

// ---------------- small PTX helpers -----------------------------------------
__device__ __forceinline__ uint32_t cvt_tf32(float f){
    uint32_t u; asm("cvt.rna.tf32.f32 %0, %1;" : "=r"(u) : "f"(f)); return u;
}
__device__ __forceinline__ void ldsm4(uint32_t a[4], uint32_t saddr){
    asm volatile("ldmatrix.sync.aligned.m8n8.x4.shared.b16 {%0,%1,%2,%3}, [%4];"
        : "=r"(a[0]),"=r"(a[1]),"=r"(a[2]),"=r"(a[3]) : "r"(saddr));
}
__device__ __forceinline__ void mma_tf32(float c[4], const uint32_t a[4],
                                         uint32_t b0, uint32_t b1){
    asm volatile(
        "mma.sync.aligned.m16n8k8.row.col.f32.tf32.tf32.f32 "
        "{%0,%1,%2,%3},{%4,%5,%6,%7},{%8,%9},{%0,%1,%2,%3};"
        : "+f"(c[0]),"+f"(c[1]),"+f"(c[2]),"+f"(c[3])
        : "r"(a[0]),"r"(a[1]),"r"(a[2]),"r"(a[3]),"r"(b0),"r"(b1));
}
__device__ __forceinline__ void cpa16(uint32_t dst, const void* src){
    asm volatile("cp.async.ca.shared.global [%0], [%1], 16;\n" :: "r"(dst), "l"(src));
}
__device__ __forceinline__ void cpa_commit(){ asm volatile("cp.async.commit_group;\n"); }
template<int N> __device__ __forceinline__ void cpa_wait(){
    asm volatile("cp.async.wait_group %0;\n" :: "n"(N));
}

// ---------------- fused prep: round x + 4 W, pack biases ---------------------
#define N4X (MTOT*EMB/4)     // 2097152
#define N4W (EMB*EMB/4)      // 262144
__device__ __forceinline__ float4 round4(float4 v){
    v.x = __uint_as_float(cvt_tf32(v.x));
    v.y = __uint_as_float(cvt_tf32(v.y));
    v.z = __uint_as_float(cvt_tf32(v.z));
    v.w = __uint_as_float(cvt_tf32(v.w));
    return v;
}
__global__ void prep_k(
    const float4* __restrict__ x,
    const float4* __restrict__ Wq, const float4* __restrict__ Wk,
    const float4* __restrict__ Wv, const float4* __restrict__ Wo,
    const float*  __restrict__ bq, const float* __restrict__ bk,
    const float*  __restrict__ bv,
    float4* __restrict__ xp, float4* __restrict__ wp, float* __restrict__ bp)
{
    int i = blockIdx.x*blockDim.x + threadIdx.x;
    if(i < N4X){
        xp[i] = round4(x[i]);
    } else if(i < N4X + 4*N4W){
        int j = i - N4X;
        int w = j >> 18;
        int off = j & (N4W-1);
        const float4* src = (w==0)?Wq : (w==1)?Wk : (w==2)?Wv : Wo;
        wp[(size_t)w*N4W + off] = round4(src[off]);
    } else {
        int j = i - (N4X + 4*N4W);
        if(j < 3*EMB){
            int seg = j >> 10, off = j & (EMB-1);
            const float* src = (seg==0)?bq : (seg==1)?bk : bv;
            bp[j] = src[off];
        }
    }
}
#define PREP_TOTAL (N4X + 4*N4W + 3*EMB)

// =============================================================================
// NT GEMM, 3-stage cp.async pipeline, ldmatrix for BOTH A and B fragments.
// fused=1: N=3072 (Wq|Wk|Wv); seg selects dest; Q scaled 1/8; V stored
//          transposed [bh][d][s]. fused=0: flat [M,1024] store.
// =============================================================================
#define GBM 128
#define GBN 64
#define GBK 32
#define ASTR 36
#define A_STAGE (GBM*ASTR)               // 4608 floats
#define B_STAGE (GBN*ASTR)               // 2304 floats
#define STG_SZ  (A_STAGE + B_STAGE)      // 6912 floats
#define GEMM_SMEM_BYTES (3*STG_SZ*4)     // 82944

__global__ __launch_bounds__(256) void gemm_nt(
    const float* __restrict__ A, const float* __restrict__ W,
    const float* __restrict__ bias,
    float* __restrict__ oQ, float* __restrict__ oK, float* __restrict__ oV,
    int fused)
{
    extern __shared__ float sm[];
    const int tid  = threadIdx.x;
    const int lane = tid & 31;
    const int wid  = tid >> 5;
    const int wm   = wid & 3, wn = wid >> 2;
    const int m0 = blockIdx.y * GBM;
    const int n0 = blockIdx.x * GBN;
    const uint32_t sbase = (uint32_t)__cvta_generic_to_shared(sm);

    auto load_stage = [&](int kt, int st){
        const int k0 = kt*GBK;
        const int base = st*STG_SZ;
        const float* ag = A + (size_t)m0*EMB + k0;
        #pragma unroll
        for(int i=0;i<4;i++){
            int idx = tid + i*256;
            int r = idx>>3, c = (idx&7)*4;
            cpa16(sbase + (uint32_t)((base + r*ASTR + c)*4),
                  ag + (size_t)r*EMB + c);
        }
        const float* wg = W + (size_t)n0*EMB + k0;
        #pragma unroll
        for(int i=0;i<2;i++){
            int idx = tid + i*256;
            int r = idx>>3, c = (idx&7)*4;
            cpa16(sbase + (uint32_t)((base + A_STAGE + r*ASTR + c)*4),
                  wg + (size_t)r*EMB + c);
        }
        cpa_commit();
    };

    // ldmatrix lane offsets
    const int bm = lane >> 3, br = lane & 7;     // B-side: matrix id, row
    uint32_t aoff[2], boff[2];
    #pragma unroll
    for(int im=0; im<2; im++){
        int r = wm*32 + im*16 + (lane&7) + ((lane>>3)&1)*8;
        aoff[im] = (uint32_t)(r*ASTR + (lane>>4)*4);
    }
    #pragma unroll
    for(int p=0; p<2; p++){
        int n = wn*32 + (2*p + (bm>>1))*8 + br;
        boff[p] = (uint32_t)(A_STAGE + n*ASTR + (bm&1)*4);
    }

    float acc[2][4][4] = {};

    load_stage(0, 0);
    load_stage(1, 1);
    const int NKT = EMB/GBK;   // 32
    for(int kt=0; kt<NKT; kt++){
        if(kt == NKT-1) cpa_wait<0>(); else cpa_wait<1>();
        __syncthreads();
        const int st = kt % 3;
        const uint32_t base = (uint32_t)(st*STG_SZ);

        #pragma unroll
        for(int ks=0; ks<4; ks++){
            uint32_t a[2][4], bf[2][4];
            ldsm4(a[0],  sbase + (base + aoff[0] + ks*8)*4);
            ldsm4(a[1],  sbase + (base + aoff[1] + ks*8)*4);
            ldsm4(bf[0], sbase + (base + boff[0] + ks*8)*4);
            ldsm4(bf[1], sbase + (base + boff[1] + ks*8)*4);
            mma_tf32(acc[0][0], a[0], bf[0][0], bf[0][1]);
            mma_tf32(acc[1][0], a[1], bf[0][0], bf[0][1]);
            mma_tf32(acc[0][1], a[0], bf[0][2], bf[0][3]);
            mma_tf32(acc[1][1], a[1], bf[0][2], bf[0][3]);
            mma_tf32(acc[0][2], a[0], bf[1][0], bf[1][1]);
            mma_tf32(acc[1][2], a[1], bf[1][0], bf[1][1]);
            mma_tf32(acc[0][3], a[0], bf[1][2], bf[1][3]);
            mma_tf32(acc[1][3], a[1], bf[1][2], bf[1][3]);
        }
        if(kt+2 < NKT) load_stage(kt+2, (kt+2)%3);
    }

    // epilogue
    int seg = 0, head = 0;
    float scale = 1.0f;
    float* outp = oQ;
    if(fused){
        seg  = blockIdx.x >> 4;
        head = blockIdx.x & 15;
        outp = (seg==0) ? oQ : (seg==1) ? oK : oV;
        scale = (seg==0) ? 0.125f : 1.0f;
    }
    #pragma unroll
    for(int im=0; im<2; im++){
        #pragma unroll
        for(int jn=0; jn<4; jn++){
            int nc = wn*32 + jn*8 + (lane&3)*2;
            float b0 = bias[n0+nc], b1 = bias[n0+nc+1];
            #pragma unroll
            for(int half=0; half<2; half++){
                int r = m0 + wm*32 + im*16 + (lane>>2) + half*8;
                float v0 = acc[im][jn][half*2+0] + b0;
                float v1 = acc[im][jn][half*2+1] + b1;
                if(fused){
                    v0 = __uint_as_float(cvt_tf32(v0*scale));
                    v1 = __uint_as_float(cvt_tf32(v1*scale));
                    int bidx = r >> 11;
                    int srow = r & (SEQ-1);
                    size_t bh = (size_t)(bidx*HEADS + head);
                    if(seg == 2){
                        // transposed: [bh][d][s]
                        outp[(bh*HDIM + nc  )*SEQ + srow] = v0;
                        outp[(bh*HDIM + nc+1)*SEQ + srow] = v1;
                    }else{
                        *(float2*)&outp[(bh*SEQ + srow)*HDIM + nc] = make_float2(v0, v1);
                    }
                }else{
                    *(float2*)&outp[(size_t)r*EMB + n0 + nc] = make_float2(v0, v1);
                }
            }
        }
    }
}

// =============================================================================
// Flash attention: 128 threads (4 warps), FBQ=128, M_warp=32.
// Q register-resident; K via ldmatrix; V stored d-major -> ldmatrix too.
// All operands pre-rounded tf32. 2 blocks/SM.
// =============================================================================
#define FBQ 128
#define FBK 64
#define KSTR 68
#define VTSTR 68          // transposed V: rows d (64), cols k (64)
#define PSTR 68
#define KS_OFF   0
#define KS_STAGE (FBK*KSTR)                 // 4352
#define VS_OFF   (2*KS_STAGE)               // 8704
#define VS_STAGE (HDIM*VTSTR)               // 4352
#define QP_OFF   (VS_OFF + 2*VS_STAGE)      // 17408
#define QP_SZ    (FBQ*PSTR)                 // 8704
#define BI_OFF   (QP_OFF + QP_SZ)           // 26112
#define FLASH_SMEM_BYTES ((BI_OFF + 128)*4) // 104960

__global__ __launch_bounds__(128, 2) void flash_attn(
    const float* __restrict__ Qg_, const float* __restrict__ Kg_,
    const float* __restrict__ Vg_, const int* __restrict__ mask,
    float* __restrict__ ctx)
{
    extern __shared__ float sm[];
    const uint32_t sbase = (uint32_t)__cvta_generic_to_shared(sm);
    const int tid = threadIdx.x, lane = tid&31, w = tid>>5;
    const int bh = blockIdx.y, b = bh>>4, h = bh&15;
    const int q0 = blockIdx.x * FBQ;
    const float* Qg = Qg_ + (size_t)bh*SEQ*HDIM;
    const float* Kg = Kg_ + (size_t)bh*SEQ*HDIM;
    const float* Vg = Vg_ + (size_t)bh*HDIM*SEQ;   // transposed [d][s]

    // Q tile -> smem (group 0)
    #pragma unroll
    for(int i=0;i<16;i++){
        int idx = tid + i*128;
        int r = idx>>4, c = (idx&15)*4;
        cpa16(sbase + (uint32_t)((QP_OFF + r*PSTR + c)*4),
              Qg + (size_t)(q0+r)*HDIM + c);
    }
    cpa_commit();

    auto loadKV = [&](int kt, int st){
        const int k0 = kt*FBK;
        #pragma unroll
        for(int i=0;i<8;i++){
            int idx = tid + i*128;
            int r = idx>>4, c = (idx&15)*4;
            cpa16(sbase + (uint32_t)((KS_OFF + st*KS_STAGE + r*KSTR + c)*4),
                  Kg + (size_t)(k0+r)*HDIM + c);
        }
        #pragma unroll
        for(int i=0;i<8;i++){
            int idx = tid + i*128;
            int r = idx>>4, c = (idx&15)*4;   // r = d row, c = k col
            cpa16(sbase + (uint32_t)((VS_OFF + st*VS_STAGE + r*VTSTR + c)*4),
                  Vg + (size_t)r*SEQ + k0 + c);
        }
        if(tid < FBK){
            int mv = mask[b*SEQ + k0 + tid];
            sm[BI_OFF + st*FBK + tid] = mv ? 0.0f : -1e9f;
        }
        cpa_commit();
    };
    loadKV(0, 0);    // group 1

    cpa_wait<1>();   // Q ready
    __syncthreads();

    // ldmatrix lane offsets
    const int bm = lane >> 3, br = lane & 7;
    uint32_t koff[4], voff[4], poff[2];
    #pragma unroll
    for(int p=0; p<4; p++){
        int n = (2*p + (bm>>1))*8 + br;
        koff[p] = (uint32_t)(n*KSTR  + (bm&1)*4);
        voff[p] = (uint32_t)(n*VTSTR + (bm&1)*4);
    }
    #pragma unroll
    for(int im=0; im<2; im++){
        int r = w*32 + im*16 + (lane&7) + ((lane>>3)&1)*8;
        poff[im] = (uint32_t)(QP_OFF + r*PSTR + (lane>>4)*4);
    }

    // Q fragments -> registers
    uint32_t qf[8][2][4];
    #pragma unroll
    for(int kd=0; kd<8; kd++){
        #pragma unroll
        for(int im=0; im<2; im++)
            ldsm4(qf[kd][im], sbase + (poff[im] + kd*8)*4);
    }

    float m_[2][2] = {{-1e30f,-1e30f},{-1e30f,-1e30f}};
    float l_[2][2] = {{0.f,0.f},{0.f,0.f}};
    float o[2][8][4] = {};

    const int NT = SEQ/FBK;   // 32
    for(int kt=0; kt<NT; kt++){
        if(kt+1 < NT){ loadKV(kt+1, (kt+1)&1); cpa_wait<1>(); }
        else         { cpa_wait<0>(); }
        __syncthreads();
        const int st = kt & 1;
        const uint32_t kb = (uint32_t)(KS_OFF + st*KS_STAGE);
        const uint32_t vb = (uint32_t)(VS_OFF + st*VS_STAGE);

        // ---- S = Q K^T ----
        float s[2][8][4] = {};
        #pragma unroll
        for(int kd=0; kd<8; kd++){
            #pragma unroll
            for(int p=0; p<4; p++){
                uint32_t kf[4];
                ldsm4(kf, sbase + (kb + koff[p] + kd*8)*4);
                mma_tf32(s[0][2*p  ], qf[kd][0], kf[0], kf[1]);
                mma_tf32(s[1][2*p  ], qf[kd][1], kf[0], kf[1]);
                mma_tf32(s[0][2*p+1], qf[kd][0], kf[2], kf[3]);
                mma_tf32(s[1][2*p+1], qf[kd][1], kf[2], kf[3]);
            }
        }

        // ---- online softmax ----
        #pragma unroll
        for(int im=0; im<2; im++){
            float tm0 = -1e30f, tm1 = -1e30f;
            #pragma unroll
            for(int jn=0; jn<8; jn++){
                int col = jn*8 + (lane&3)*2;
                float bb0 = sm[BI_OFF + st*FBK + col];
                float bb1 = sm[BI_OFF + st*FBK + col+1];
                s[im][jn][0] += bb0; tm0 = fmaxf(tm0, s[im][jn][0]);
                s[im][jn][1] += bb1; tm0 = fmaxf(tm0, s[im][jn][1]);
                s[im][jn][2] += bb0; tm1 = fmaxf(tm1, s[im][jn][2]);
                s[im][jn][3] += bb1; tm1 = fmaxf(tm1, s[im][jn][3]);
            }
            tm0 = fmaxf(tm0, __shfl_xor_sync(0xffffffffu, tm0, 1));
            tm0 = fmaxf(tm0, __shfl_xor_sync(0xffffffffu, tm0, 2));
            tm1 = fmaxf(tm1, __shfl_xor_sync(0xffffffffu, tm1, 1));
            tm1 = fmaxf(tm1, __shfl_xor_sync(0xffffffffu, tm1, 2));
            float mn0 = fmaxf(m_[im][0], tm0), mn1 = fmaxf(m_[im][1], tm1);
            float al0 = __expf(m_[im][0]-mn0), al1 = __expf(m_[im][1]-mn1);
            m_[im][0] = mn0; m_[im][1] = mn1;
            float rs0 = 0.f, rs1 = 0.f;
            #pragma unroll
            for(int jn=0; jn<8; jn++){
                s[im][jn][0] = __expf(s[im][jn][0]-mn0); rs0 += s[im][jn][0];
                s[im][jn][1] = __expf(s[im][jn][1]-mn0); rs0 += s[im][jn][1];
                s[im][jn][2] = __expf(s[im][jn][2]-mn1); rs1 += s[im][jn][2];
                s[im][jn][3] = __expf(s[im][jn][3]-mn1); rs1 += s[im][jn][3];
            }
            rs0 += __shfl_xor_sync(0xffffffffu, rs0, 1);
            rs0 += __shfl_xor_sync(0xffffffffu, rs0, 2);
            rs1 += __shfl_xor_sync(0xffffffffu, rs1, 1);
            rs1 += __shfl_xor_sync(0xffffffffu, rs1, 2);
            l_[im][0] = l_[im][0]*al0 + rs0;
            l_[im][1] = l_[im][1]*al1 + rs1;
            #pragma unroll
            for(int jd=0; jd<8; jd++){
                o[im][jd][0]*=al0; o[im][jd][1]*=al0;
                o[im][jd][2]*=al1; o[im][jd][3]*=al1;
            }
        }

        // ---- P (rounded) -> smem, reusing Q region (warp-exclusive rows) ----
        #pragma unroll
        for(int im=0; im<2; im++){
            int pr = w*32 + im*16 + (lane>>2);
            #pragma unroll
            for(int jn=0; jn<8; jn++){
                int cc = jn*8 + (lane&3)*2;
                *(float2*)&sm[QP_OFF + pr*PSTR + cc] = make_float2(
                    __uint_as_float(cvt_tf32(s[im][jn][0])),
                    __uint_as_float(cvt_tf32(s[im][jn][1])));
                *(float2*)&sm[QP_OFF + (pr+8)*PSTR + cc] = make_float2(
                    __uint_as_float(cvt_tf32(s[im][jn][2])),
                    __uint_as_float(cvt_tf32(s[im][jn][3])));
            }
        }
        __syncwarp();

        // ---- O += P V ----
        #pragma unroll
        for(int kk=0; kk<8; kk++){
            uint32_t pf[2][4];
            ldsm4(pf[0], sbase + (poff[0] + kk*8)*4);
            ldsm4(pf[1], sbase + (poff[1] + kk*8)*4);
            #pragma unroll
            for(int p=0; p<4; p++){
                uint32_t vf[4];
                ldsm4(vf, sbase + (vb + voff[p] + kk*8)*4);
                mma_tf32(o[0][2*p  ], pf[0], vf[0], vf[1]);
                mma_tf32(o[1][2*p  ], pf[1], vf[0], vf[1]);
                mma_tf32(o[0][2*p+1], pf[0], vf[2], vf[3]);
                mma_tf32(o[1][2*p+1], pf[1], vf[2], vf[3]);
            }
        }
        __syncthreads();
    }

    // epilogue -> ctx [B,S,E], rounded for the output GEMM
    #pragma unroll
    for(int im=0; im<2; im++){
        float inv0 = 1.0f/l_[im][0], inv1 = 1.0f/l_[im][1];
        int gr0 = q0 + w*32 + im*16 + (lane>>2);
        #pragma unroll
        for(int jd=0; jd<8; jd++){
            int col = h*HDIM + jd*8 + (lane&3)*2;
            *(float2*)&ctx[(size_t)(b*SEQ + gr0  )*EMB + col] = make_float2(
                __uint_as_float(cvt_tf32(o[im][jd][0]*inv0)),
                __uint_as_float(cvt_tf32(o[im][jd][1]*inv0)));
            *(float2*)&ctx[(size_t)(b*SEQ + gr0+8)*EMB + col] = make_float2(
                __uint_as_float(cvt_tf32(o[im][jd][2]*inv1)),
                __uint_as_float(cvt_tf32(o[im][jd][3]*inv1)));
        }
    }
}

// =============================================================================
extern "C" void kernel_launch(void* const* d_in, const int* in_sizes, int n_in,
                              void* d_out, int out_size)
{
    const float* x    = (const float*)d_in[0];
    const int*   mask = (const int*)  d_in[1];
    const float* Wq   = (const float*)d_in[2];
    const float* bq   = (const float*)d_in[3];
    const float* Wk   = (const float*)d_in[4];
    const float* bk   = (const float*)d_in[5];
    const float* Wv   = (const float*)d_in[6];
    const float* bv   = (const float*)d_in[7];
    const float* Wo   = (const float*)d_in[8];
    const float* bo   = (const float*)d_in[9];
    float* out = (float*)d_out;

    float *qp, *kp, *vp, *cp, *xp, *wp, *bp;
    cudaGetSymbolAddress((void**)&qp, g_q);
    cudaGetSymbolAddress((void**)&kp, g_k);
    cudaGetSymbolAddress((void**)&vp, g_v);
    cudaGetSymbolAddress((void**)&cp, g_ctx);
    cudaGetSymbolAddress((void**)&xp, g_x);
    cudaGetSymbolAddress((void**)&wp, g_w);
    cudaGetSymbolAddress((void**)&bp, g_b);

    cudaFuncSetAttribute(gemm_nt,   cudaFuncAttributeMaxDynamicSharedMemorySize, GEMM_SMEM_BYTES);
    cudaFuncSetAttribute(flash_attn,cudaFuncAttributeMaxDynamicSharedMemorySize, FLASH_SMEM_BYTES);

    // 1) fused prep (single launch)
    prep_k<<<(PREP_TOTAL+255)/256, 256>>>(
        (const float4*)x, (const float4*)Wq, (const float4*)Wk,
        (const float4*)Wv, (const float4*)Wo,
        bq, bk, bv,
        (float4*)xp, (float4*)wp, bp);

    // 2) fused QKV projection (N=3072)
    dim3 gqkv(3*EMB/GBN, MTOT/GBM);  // (48, 64)
    gemm_nt<<<gqkv, 256, GEMM_SMEM_BYTES>>>(xp, wp, bp, qp, kp, vp, 1);

    // 3) flash attention
    dim3 fg(SEQ/FBQ, BATCH*HEADS);   // (16, 64)
    flash_attn<<<fg, 128, FLASH_SMEM_BYTES>>>(qp, kp, vp, mask, cp);

    // 4) output projection
    dim3 go(EMB/GBN, MTOT/GBM);      // (16, 64)
    gemm_nt<<<go, 256, GEMM_SMEM_BYTES>>>(cp, wp+3*(size_t)EMB*EMB, bo, out, nullptr, nullptr, 0);
}

// round 9
// speedup vs baseline: 1.2677x; 1.0238x over previous
#include <cuda_runtime.h>
#include <cstdint>

#define BATCH 4
#define SEQ   2048
#define EMB   1024
#define HEADS 16
#define HDIM  64
#define MTOT  (BATCH*SEQ)   // 8192

// ---------------- scratch (device globals: allocation-free rule) -------------
__device__ float g_q[MTOT*EMB];       // tf32-rounded, pre-scaled 1/8, [bh][s][d]
__device__ float g_k[MTOT*EMB];       // tf32-rounded, [bh][s][d]
__device__ float g_v[MTOT*EMB];       // tf32-rounded, TRANSPOSED [bh][d][s]
__device__ float g_ctx[MTOT*EMB];     // tf32-rounded, [B,S,E]
__device__ float g_x[MTOT*EMB];       // tf32-rounded input
__device__ float g_w[4*EMB*EMB];      // tf32-rounded Wq,Wk,Wv,Wo (contiguous)
__device__ float g_b[3*EMB];          // packed bq|bk|bv

// ---------------- PTX helpers ------------------------------------------------
__device__ __forceinline__ uint32_t cvt_tf32(float f){
    uint32_t u; asm("cvt.rna.tf32.f32 %0, %1;" : "=r"(u) : "f"(f)); return u;
}
__device__ __forceinline__ float rt(float f){ return __uint_as_float(cvt_tf32(f)); }
__device__ __forceinline__ void ldsm4(uint32_t a[4], uint32_t saddr){
    asm volatile("ldmatrix.sync.aligned.m8n8.x4.shared.b16 {%0,%1,%2,%3}, [%4];"
        : "=r"(a[0]),"=r"(a[1]),"=r"(a[2]),"=r"(a[3]) : "r"(saddr));
}
__device__ __forceinline__ void mma_tf32(float c[4], const uint32_t a[4],
                                         uint32_t b0, uint32_t b1){
    asm volatile(
        "mma.sync.aligned.m16n8k8.row.col.f32.tf32.tf32.f32 "
        "{%0,%1,%2,%3},{%4,%5,%6,%7},{%8,%9},{%0,%1,%2,%3};"
        : "+f"(c[0]),"+f"(c[1]),"+f"(c[2]),"+f"(c[3])
        : "r"(a[0]),"r"(a[1]),"r"(a[2]),"r"(a[3]),"r"(b0),"r"(b1));
}
__device__ __forceinline__ void cpa16(uint32_t dst, const void* src){
    asm volatile("cp.async.ca.shared.global [%0], [%1], 16;\n" :: "r"(dst), "l"(src));
}
__device__ __forceinline__ void cpa_commit(){ asm volatile("cp.async.commit_group;\n"); }
template<int N> __device__ __forceinline__ void cpa_wait(){
    asm volatile("cp.async.wait_group %0;\n" :: "n"(N));
}

// ---------------- fused prep: round x + 4 W, pack biases ---------------------
#define N4X (MTOT*EMB/4)     // 2097152
#define N4W (EMB*EMB/4)      // 262144
__device__ __forceinline__ float4 round4(float4 v){
    v.x = rt(v.x); v.y = rt(v.y); v.z = rt(v.z); v.w = rt(v.w);
    return v;
}
__global__ void prep_k(
    const float4* __restrict__ x,
    const float4* __restrict__ Wq, const float4* __restrict__ Wk,
    const float4* __restrict__ Wv, const float4* __restrict__ Wo,
    const float*  __restrict__ bq, const float* __restrict__ bk,
    const float*  __restrict__ bv,
    float4* __restrict__ xp, float4* __restrict__ wp, float* __restrict__ bp)
{
    int i = blockIdx.x*blockDim.x + threadIdx.x;
    if(i < N4X){
        xp[i] = round4(x[i]);
    } else if(i < N4X + 4*N4W){
        int j = i - N4X;
        int w = j >> 18;
        int off = j & (N4W-1);
        const float4* src = (w==0)?Wq : (w==1)?Wk : (w==2)?Wv : Wo;
        wp[(size_t)w*N4W + off] = round4(src[off]);
    } else {
        int j = i - (N4X + 4*N4W);
        if(j < 3*EMB){
            int seg = j >> 10, off = j & (EMB-1);
            const float* src = (seg==0)?bq : (seg==1)?bk : bv;
            bp[j] = src[off];
        }
    }
}
#define PREP_TOTAL (N4X + 4*N4W + 3*EMB)

// =============================================================================
// NT GEMM v3: 128x128 block, 4 warps (2x2), warp tile 64x64 -> 0.125 B/MAC.
// 3-stage cp.async, ldmatrix both operands, one __syncthreads per k-iter.
// fused=1: N=3072 (Wq|Wk|Wv); Q scaled 1/8; V stored transposed [bh][d][s].
// fused=0: flat [M,1024] store.
// =============================================================================
#define GBM 128
#define GBN 128
#define GBK 32
#define ASTR 36
#define A_STAGE (GBM*ASTR)               // 4608 floats
#define B_STAGE (GBN*ASTR)               // 4608 floats
#define STG_SZ  (A_STAGE + B_STAGE)      // 9216 floats = 36 KB
#define GEMM_SMEM_BYTES (3*STG_SZ*4)     // 110592 B

__global__ __launch_bounds__(128, 2) void gemm_nt(
    const float* __restrict__ A, const float* __restrict__ W,
    const float* __restrict__ bias,
    float* __restrict__ oQ, float* __restrict__ oK, float* __restrict__ oV,
    int fused)
{
    extern __shared__ float sm[];
    const int tid  = threadIdx.x;
    const int lane = tid & 31;
    const int wid  = tid >> 5;
    const int wm   = wid & 1, wn = wid >> 1;   // 2x2 warps
    const int m0 = blockIdx.y * GBM;
    const int n0 = blockIdx.x * GBN;
    const uint32_t sbase = (uint32_t)__cvta_generic_to_shared(sm);

    auto load_stage = [&](int kt, int st){
        const int k0 = kt*GBK;
        const int base = st*STG_SZ;
        const float* ag = A + (size_t)m0*EMB + k0;
        #pragma unroll
        for(int i=0;i<8;i++){
            int idx = tid + i*128;
            int r = idx>>3, c = (idx&7)*4;
            cpa16(sbase + (uint32_t)((base + r*ASTR + c)*4),
                  ag + (size_t)r*EMB + c);
        }
        const float* wg = W + (size_t)n0*EMB + k0;
        #pragma unroll
        for(int i=0;i<8;i++){
            int idx = tid + i*128;
            int r = idx>>3, c = (idx&7)*4;
            cpa16(sbase + (uint32_t)((base + A_STAGE + r*ASTR + c)*4),
                  wg + (size_t)r*EMB + c);
        }
        cpa_commit();
    };

    // ldmatrix lane offsets
    const int bm = lane >> 3, br = lane & 7;
    uint32_t aoff[4], boff[4];
    #pragma unroll
    for(int im=0; im<4; im++){
        int r = wm*64 + im*16 + (lane&7) + ((lane>>3)&1)*8;
        aoff[im] = (uint32_t)(r*ASTR + (lane>>4)*4);
    }
    #pragma unroll
    for(int p=0; p<4; p++){
        int n = wn*64 + (2*p + (bm>>1))*8 + br;
        boff[p] = (uint32_t)(A_STAGE + n*ASTR + (bm&1)*4);
    }

    float acc[4][8][4] = {};

    load_stage(0, 0);
    load_stage(1, 1);
    const int NKT = EMB/GBK;   // 32
    for(int kt=0; kt<NKT; kt++){
        if(kt == NKT-1) cpa_wait<0>(); else cpa_wait<1>();
        __syncthreads();
        const uint32_t base = (uint32_t)((kt % 3)*STG_SZ);

        #pragma unroll
        for(int ks=0; ks<4; ks++){
            uint32_t a[4][4];
            #pragma unroll
            for(int im=0; im<4; im++)
                ldsm4(a[im], sbase + (base + aoff[im] + ks*8)*4);
            #pragma unroll
            for(int p=0; p<4; p++){
                uint32_t bf[4];
                ldsm4(bf, sbase + (base + boff[p] + ks*8)*4);
                #pragma unroll
                for(int im=0; im<4; im++){
                    mma_tf32(acc[im][2*p  ], a[im], bf[0], bf[1]);
                    mma_tf32(acc[im][2*p+1], a[im], bf[2], bf[3]);
                }
            }
        }
        if(kt+2 < NKT) load_stage(kt+2, (kt+2)%3);
    }

    // ---- epilogue (direct from registers) ----
    int seg = 0;
    float scale = 1.0f;
    float* outp = oQ;
    int n0s = n0;
    if(fused){
        seg  = n0 >> 10;
        n0s  = n0 & 1023;
        outp = (seg==0) ? oQ : (seg==1) ? oK : oV;
        scale = (seg==0) ? 0.125f : 1.0f;
    }
    #pragma unroll
    for(int im=0; im<4; im++){
        #pragma unroll
        for(int jn=0; jn<8; jn++){
            int nc = wn*64 + jn*8 + (lane&3)*2;
            float b0 = bias[n0+nc], b1 = bias[n0+nc+1];
            #pragma unroll
            for(int half=0; half<2; half++){
                int r = m0 + wm*64 + im*16 + (lane>>2) + half*8;
                float v0 = acc[im][jn][half*2+0] + b0;
                float v1 = acc[im][jn][half*2+1] + b1;
                if(fused){
                    v0 = rt(v0*scale);
                    v1 = rt(v1*scale);
                    int bidx = r >> 11;
                    int srow = r & (SEQ-1);
                    int ncol = n0s + nc;
                    int head = ncol >> 6, d = ncol & 63;
                    size_t bh = (size_t)(bidx*HEADS + head);
                    if(seg == 2){
                        outp[(bh*HDIM + d  )*SEQ + srow] = v0;
                        outp[(bh*HDIM + d+1)*SEQ + srow] = v1;
                    }else{
                        *(float2*)&outp[(bh*SEQ + srow)*HDIM + d] = make_float2(v0, v1);
                    }
                }else{
                    *(float2*)&outp[(size_t)r*EMB + n0 + nc] = make_float2(v0, v1);
                }
            }
        }
    }
}

// =============================================================================
// Flash attention (unchanged): 128 threads, FBQ=128, M_warp=32,
// Q register-resident, K/V(P) via ldmatrix, V d-major, tf32 pre-rounded.
// =============================================================================
#define FBQ 128
#define FBK 64
#define KSTR 68
#define VTSTR 68
#define PSTR 68
#define KS_OFF   0
#define KS_STAGE (FBK*KSTR)
#define VS_OFF   (2*KS_STAGE)
#define VS_STAGE (HDIM*VTSTR)
#define QP_OFF   (VS_OFF + 2*VS_STAGE)
#define QP_SZ    (FBQ*PSTR)
#define BI_OFF   (QP_OFF + QP_SZ)
#define FLASH_SMEM_BYTES ((BI_OFF + 128)*4)

__global__ __launch_bounds__(128, 2) void flash_attn(
    const float* __restrict__ Qg_, const float* __restrict__ Kg_,
    const float* __restrict__ Vg_, const int* __restrict__ mask,
    float* __restrict__ ctx)
{
    extern __shared__ float sm[];
    const uint32_t sbase = (uint32_t)__cvta_generic_to_shared(sm);
    const int tid = threadIdx.x, lane = tid&31, w = tid>>5;
    const int bh = blockIdx.y, b = bh>>4, h = bh&15;
    const int q0 = blockIdx.x * FBQ;
    const float* Qg = Qg_ + (size_t)bh*SEQ*HDIM;
    const float* Kg = Kg_ + (size_t)bh*SEQ*HDIM;
    const float* Vg = Vg_ + (size_t)bh*HDIM*SEQ;

    #pragma unroll
    for(int i=0;i<16;i++){
        int idx = tid + i*128;
        int r = idx>>4, c = (idx&15)*4;
        cpa16(sbase + (uint32_t)((QP_OFF + r*PSTR + c)*4),
              Qg + (size_t)(q0+r)*HDIM + c);
    }
    cpa_commit();

    auto loadKV = [&](int kt, int st){
        const int k0 = kt*FBK;
        #pragma unroll
        for(int i=0;i<8;i++){
            int idx = tid + i*128;
            int r = idx>>4, c = (idx&15)*4;
            cpa16(sbase + (uint32_t)((KS_OFF + st*KS_STAGE + r*KSTR + c)*4),
                  Kg + (size_t)(k0+r)*HDIM + c);
        }
        #pragma unroll
        for(int i=0;i<8;i++){
            int idx = tid + i*128;
            int r = idx>>4, c = (idx&15)*4;
            cpa16(sbase + (uint32_t)((VS_OFF + st*VS_STAGE + r*VTSTR + c)*4),
                  Vg + (size_t)r*SEQ + k0 + c);
        }
        if(tid < FBK){
            int mv = mask[b*SEQ + k0 + tid];
            sm[BI_OFF + st*FBK + tid] = mv ? 0.0f : -1e9f;
        }
        cpa_commit();
    };
    loadKV(0, 0);

    cpa_wait<1>();
    __syncthreads();

    const int bm = lane >> 3, br = lane & 7;
    uint32_t koff[4], voff[4], poff[2];
    #pragma unroll
    for(int p=0; p<4; p++){
        int n = (2*p + (bm>>1))*8 + br;
        koff[p] = (uint32_t)(n*KSTR  + (bm&1)*4);
        voff[p] = (uint32_t)(n*VTSTR + (bm&1)*4);
    }
    #pragma unroll
    for(int im=0; im<2; im++){
        int r = w*32 + im*16 + (lane&7) + ((lane>>3)&1)*8;
        poff[im] = (uint32_t)(QP_OFF + r*PSTR + (lane>>4)*4);
    }

    uint32_t qf[8][2][4];
    #pragma unroll
    for(int kd=0; kd<8; kd++){
        #pragma unroll
        for(int im=0; im<2; im++)
            ldsm4(qf[kd][im], sbase + (poff[im] + kd*8)*4);
    }

    float m_[2][2] = {{-1e30f,-1e30f},{-1e30f,-1e30f}};
    float l_[2][2] = {{0.f,0.f},{0.f,0.f}};
    float o[2][8][4] = {};

    const int NT = SEQ/FBK;
    for(int kt=0; kt<NT; kt++){
        if(kt+1 < NT){ loadKV(kt+1, (kt+1)&1); cpa_wait<1>(); }
        else         { cpa_wait<0>(); }
        __syncthreads();
        const int st = kt & 1;
        const uint32_t kb = (uint32_t)(KS_OFF + st*KS_STAGE);
        const uint32_t vb = (uint32_t)(VS_OFF + st*VS_STAGE);

        float s[2][8][4] = {};
        #pragma unroll
        for(int kd=0; kd<8; kd++){
            #pragma unroll
            for(int p=0; p<4; p++){
                uint32_t kf[4];
                ldsm4(kf, sbase + (kb + koff[p] + kd*8)*4);
                mma_tf32(s[0][2*p  ], qf[kd][0], kf[0], kf[1]);
                mma_tf32(s[1][2*p  ], qf[kd][1], kf[0], kf[1]);
                mma_tf32(s[0][2*p+1], qf[kd][0], kf[2], kf[3]);
                mma_tf32(s[1][2*p+1], qf[kd][1], kf[2], kf[3]);
            }
        }

        #pragma unroll
        for(int im=0; im<2; im++){
            float tm0 = -1e30f, tm1 = -1e30f;
            #pragma unroll
            for(int jn=0; jn<8; jn++){
                int col = jn*8 + (lane&3)*2;
                float bb0 = sm[BI_OFF + st*FBK + col];
                float bb1 = sm[BI_OFF + st*FBK + col+1];
                s[im][jn][0] += bb0; tm0 = fmaxf(tm0, s[im][jn][0]);
                s[im][jn][1] += bb1; tm0 = fmaxf(tm0, s[im][jn][1]);
                s[im][jn][2] += bb0; tm1 = fmaxf(tm1, s[im][jn][2]);
                s[im][jn][3] += bb1; tm1 = fmaxf(tm1, s[im][jn][3]);
            }
            tm0 = fmaxf(tm0, __shfl_xor_sync(0xffffffffu, tm0, 1));
            tm0 = fmaxf(tm0, __shfl_xor_sync(0xffffffffu, tm0, 2));
            tm1 = fmaxf(tm1, __shfl_xor_sync(0xffffffffu, tm1, 1));
            tm1 = fmaxf(tm1, __shfl_xor_sync(0xffffffffu, tm1, 2));
            float mn0 = fmaxf(m_[im][0], tm0), mn1 = fmaxf(m_[im][1], tm1);
            float al0 = __expf(m_[im][0]-mn0), al1 = __expf(m_[im][1]-mn1);
            m_[im][0] = mn0; m_[im][1] = mn1;
            float rs0 = 0.f, rs1 = 0.f;
            #pragma unroll
            for(int jn=0; jn<8; jn++){
                s[im][jn][0] = __expf(s[im][jn][0]-mn0); rs0 += s[im][jn][0];
                s[im][jn][1] = __expf(s[im][jn][1]-mn0); rs0 += s[im][jn][1];
                s[im][jn][2] = __expf(s[im][jn][2]-mn1); rs1 += s[im][jn][2];
                s[im][jn][3] = __expf(s[im][jn][3]-mn1); rs1 += s[im][jn][3];
            }
            rs0 += __shfl_xor_sync(0xffffffffu, rs0, 1);
            rs0 += __shfl_xor_sync(0xffffffffu, rs0, 2);
            rs1 += __shfl_xor_sync(0xffffffffu, rs1, 1);
            rs1 += __shfl_xor_sync(0xffffffffu, rs1, 2);
            l_[im][0] = l_[im][0]*al0 + rs0;
            l_[im][1] = l_[im][1]*al1 + rs1;
            #pragma unroll
            for(int jd=0; jd<8; jd++){
                o[im][jd][0]*=al0; o[im][jd][1]*=al0;
                o[im][jd][2]*=al1; o[im][jd][3]*=al1;
            }
        }

        #pragma unroll
        for(int im=0; im<2; im++){
            int pr = w*32 + im*16 + (lane>>2);
            #pragma unroll
            for(int jn=0; jn<8; jn++){
                int cc = jn*8 + (lane&3)*2;
                *(float2*)&sm[QP_OFF + pr*PSTR + cc] = make_float2(
                    rt(s[im][jn][0]), rt(s[im][jn][1]));
                *(float2*)&sm[QP_OFF + (pr+8)*PSTR + cc] = make_float2(
                    rt(s[im][jn][2]), rt(s[im][jn][3]));
            }
        }
        __syncwarp();

        #pragma unroll
        for(int kk=0; kk<8; kk++){
            uint32_t pf[2][4];
            ldsm4(pf[0], sbase + (poff[0] + kk*8)*4);
            ldsm4(pf[1], sbase + (poff[1] + kk*8)*4);
            #pragma unroll
            for(int p=0; p<4; p++){
                uint32_t vf[4];
                ldsm4(vf, sbase + (vb + voff[p] + kk*8)*4);
                mma_tf32(o[0][2*p  ], pf[0], vf[0], vf[1]);
                mma_tf32(o[1][2*p  ], pf[1], vf[0], vf[1]);
                mma_tf32(o[0][2*p+1], pf[0], vf[2], vf[3]);
                mma_tf32(o[1][2*p+1], pf[1], vf[2], vf[3]);
            }
        }
        __syncthreads();
    }

    #pragma unroll
    for(int im=0; im<2; im++){
        float inv0 = 1.0f/l_[im][0], inv1 = 1.0f/l_[im][1];
        int gr0 = q0 + w*32 + im*16 + (lane>>2);
        #pragma unroll
        for(int jd=0; jd<8; jd++){
            int col = h*HDIM + jd*8 + (lane&3)*2;
            *(float2*)&ctx[(size_t)(b*SEQ + gr0  )*EMB + col] = make_float2(
                rt(o[im][jd][0]*inv0), rt(o[im][jd][1]*inv0));
            *(float2*)&ctx[(size_t)(b*SEQ + gr0+8)*EMB + col] = make_float2(
                rt(o[im][jd][2]*inv1), rt(o[im][jd][3]*inv1));
        }
    }
}

// =============================================================================
extern "C" void kernel_launch(void* const* d_in, const int* in_sizes, int n_in,
                              void* d_out, int out_size)
{
    const float* x    = (const float*)d_in[0];
    const int*   mask = (const int*)  d_in[1];
    const float* Wq   = (const float*)d_in[2];
    const float* bq   = (const float*)d_in[3];
    const float* Wk   = (const float*)d_in[4];
    const float* bk   = (const float*)d_in[5];
    const float* Wv   = (const float*)d_in[6];
    const float* bv   = (const float*)d_in[7];
    const float* Wo   = (const float*)d_in[8];
    const float* bo   = (const float*)d_in[9];
    float* out = (float*)d_out;

    float *qp, *kp, *vp, *cp, *xp, *wp, *bp;
    cudaGetSymbolAddress((void**)&qp, g_q);
    cudaGetSymbolAddress((void**)&kp, g_k);
    cudaGetSymbolAddress((void**)&vp, g_v);
    cudaGetSymbolAddress((void**)&cp, g_ctx);
    cudaGetSymbolAddress((void**)&xp, g_x);
    cudaGetSymbolAddress((void**)&wp, g_w);
    cudaGetSymbolAddress((void**)&bp, g_b);

    cudaFuncSetAttribute(gemm_nt,   cudaFuncAttributeMaxDynamicSharedMemorySize, GEMM_SMEM_BYTES);
    cudaFuncSetAttribute(flash_attn,cudaFuncAttributeMaxDynamicSharedMemorySize, FLASH_SMEM_BYTES);

    // 1) fused prep
    prep_k<<<(PREP_TOTAL+255)/256, 256>>>(
        (const float4*)x, (const float4*)Wq, (const float4*)Wk,
        (const float4*)Wv, (const float4*)Wo,
        bq, bk, bv,
        (float4*)xp, (float4*)wp, bp);

    // 2) fused QKV projection (N=3072)
    dim3 gqkv(3*EMB/GBN, MTOT/GBM);  // (24, 64)
    gemm_nt<<<gqkv, 128, GEMM_SMEM_BYTES>>>(xp, wp, bp, qp, kp, vp, 1);

    // 3) flash attention
    dim3 fg(SEQ/FBQ, BATCH*HEADS);   // (16, 64)
    flash_attn<<<fg, 128, FLASH_SMEM_BYTES>>>(qp, kp, vp, mask, cp);

    // 4) output projection
    dim3 go(EMB/GBN, MTOT/GBM);      // (8, 64)
    gemm_nt<<<go, 128, GEMM_SMEM_BYTES>>>(cp, wp+3*(size_t)EMB*EMB, bo, out, nullptr, nullptr, 0);
}

// round 10
// speedup vs baseline: 1.2763x; 1.0068x over previous
#include <cuda_runtime.h>
#include <cstdint>

#define BATCH 4
#define SEQ   2048
#define EMB   1024
#define HEADS 16
#define HDIM  64
#define MTOT  (BATCH*SEQ)   // 8192

// ---------------- scratch (device globals: allocation-free rule) -------------
__device__ float g_q[MTOT*EMB];       // tf32-rounded, pre-scaled 1/8, [bh][s][d]
__device__ float g_k[MTOT*EMB];       // tf32-rounded, [bh][s][d]
__device__ float g_v[MTOT*EMB];       // tf32-rounded, TRANSPOSED [bh][d][s]
__device__ float g_ctx[MTOT*EMB];     // tf32-rounded, [B,S,E]
__device__ float g_x[MTOT*EMB];       // tf32-rounded input
__device__ float g_w[4*EMB*EMB];      // tf32-rounded Wq,Wk,Wv,Wo (contiguous)
__device__ float g_b[3*EMB];          // packed bq|bk|bv

// ---------------- PTX helpers ------------------------------------------------
__device__ __forceinline__ uint32_t cvt_tf32(float f){
    uint32_t u; asm("cvt.rna.tf32.f32 %0, %1;" : "=r"(u) : "f"(f)); return u;
}
__device__ __forceinline__ float rt(float f){ return __uint_as_float(cvt_tf32(f)); }
__device__ __forceinline__ void ldsm4(uint32_t a[4], uint32_t saddr){
    asm volatile("ldmatrix.sync.aligned.m8n8.x4.shared.b16 {%0,%1,%2,%3}, [%4];"
        : "=r"(a[0]),"=r"(a[1]),"=r"(a[2]),"=r"(a[3]) : "r"(saddr));
}
__device__ __forceinline__ void mma_tf32(float c[4], const uint32_t a[4],
                                         uint32_t b0, uint32_t b1){
    asm volatile(
        "mma.sync.aligned.m16n8k8.row.col.f32.tf32.tf32.f32 "
        "{%0,%1,%2,%3},{%4,%5,%6,%7},{%8,%9},{%0,%1,%2,%3};"
        : "+f"(c[0]),"+f"(c[1]),"+f"(c[2]),"+f"(c[3])
        : "r"(a[0]),"r"(a[1]),"r"(a[2]),"r"(a[3]),"r"(b0),"r"(b1));
}
__device__ __forceinline__ void cpa16(uint32_t dst, const void* src){
    asm volatile("cp.async.ca.shared.global [%0], [%1], 16;\n" :: "r"(dst), "l"(src));
}
__device__ __forceinline__ void cpa_commit(){ asm volatile("cp.async.commit_group;\n"); }
template<int N> __device__ __forceinline__ void cpa_wait(){
    asm volatile("cp.async.wait_group %0;\n" :: "n"(N));
}

// ---------------- fused prep: round x + 4 W, pack biases ---------------------
#define N4X (MTOT*EMB/4)     // 2097152
#define N4W (EMB*EMB/4)      // 262144
__device__ __forceinline__ float4 round4(float4 v){
    v.x = rt(v.x); v.y = rt(v.y); v.z = rt(v.z); v.w = rt(v.w);
    return v;
}
__global__ void prep_k(
    const float4* __restrict__ x,
    const float4* __restrict__ Wq, const float4* __restrict__ Wk,
    const float4* __restrict__ Wv, const float4* __restrict__ Wo,
    const float*  __restrict__ bq, const float* __restrict__ bk,
    const float*  __restrict__ bv,
    float4* __restrict__ xp, float4* __restrict__ wp, float* __restrict__ bp)
{
    int i = blockIdx.x*blockDim.x + threadIdx.x;
    if(i < N4X){
        xp[i] = round4(x[i]);
    } else if(i < N4X + 4*N4W){
        int j = i - N4X;
        int w = j >> 18;
        int off = j & (N4W-1);
        const float4* src = (w==0)?Wq : (w==1)?Wk : (w==2)?Wv : Wo;
        wp[(size_t)w*N4W + off] = round4(src[off]);
    } else {
        int j = i - (N4X + 4*N4W);
        if(j < 3*EMB){
            int seg = j >> 10, off = j & (EMB-1);
            const float* src = (seg==0)?bq : (seg==1)?bk : bv;
            bp[j] = src[off];
        }
    }
}
#define PREP_TOTAL (N4X + 4*N4W + 3*EMB)

// =============================================================================
// NT GEMM v4: 128x128 block, 8 warps (2x4), warp tile 64x32.
// 4 warps/SMSP for latency hiding; 3-stage cp.async; ldmatrix both operands.
// fused=1: N=3072 (Wq|Wk|Wv); Q scaled 1/8; V stored transposed [bh][d][s].
// fused=0: flat [M,1024] store.
// =============================================================================
#define GBM 128
#define GBN 128
#define GBK 32
#define ASTR 36
#define A_STAGE (GBM*ASTR)               // 4608 floats
#define B_STAGE (GBN*ASTR)               // 4608 floats
#define STG_SZ  (A_STAGE + B_STAGE)      // 9216 floats = 36 KB
#define GEMM_SMEM_BYTES (3*STG_SZ*4)     // 110592 B

__global__ __launch_bounds__(256, 2) void gemm_nt(
    const float* __restrict__ A, const float* __restrict__ W,
    const float* __restrict__ bias,
    float* __restrict__ oQ, float* __restrict__ oK, float* __restrict__ oV,
    int fused)
{
    extern __shared__ float sm[];
    const int tid  = threadIdx.x;
    const int lane = tid & 31;
    const int wid  = tid >> 5;
    const int wm   = wid & 1, wn = wid >> 1;   // 2 (M) x 4 (N) warps
    const int m0 = blockIdx.y * GBM;
    const int n0 = blockIdx.x * GBN;
    const uint32_t sbase = (uint32_t)__cvta_generic_to_shared(sm);

    auto load_stage = [&](int kt, int st){
        const int k0 = kt*GBK;
        const int base = st*STG_SZ;
        const float* ag = A + (size_t)m0*EMB + k0;
        #pragma unroll
        for(int i=0;i<4;i++){
            int idx = tid + i*256;
            int r = idx>>3, c = (idx&7)*4;
            cpa16(sbase + (uint32_t)((base + r*ASTR + c)*4),
                  ag + (size_t)r*EMB + c);
        }
        const float* wg = W + (size_t)n0*EMB + k0;
        #pragma unroll
        for(int i=0;i<4;i++){
            int idx = tid + i*256;
            int r = idx>>3, c = (idx&7)*4;
            cpa16(sbase + (uint32_t)((base + A_STAGE + r*ASTR + c)*4),
                  wg + (size_t)r*EMB + c);
        }
        cpa_commit();
    };

    // ldmatrix lane offsets
    const int bm = lane >> 3, br = lane & 7;
    uint32_t aoff[4], boff[2];
    #pragma unroll
    for(int im=0; im<4; im++){
        int r = wm*64 + im*16 + (lane&7) + ((lane>>3)&1)*8;
        aoff[im] = (uint32_t)(r*ASTR + (lane>>4)*4);
    }
    #pragma unroll
    for(int p=0; p<2; p++){
        int n = wn*32 + (2*p + (bm>>1))*8 + br;
        boff[p] = (uint32_t)(A_STAGE + n*ASTR + (bm&1)*4);
    }

    float acc[4][4][4] = {};

    load_stage(0, 0);
    load_stage(1, 1);
    const int NKT = EMB/GBK;   // 32
    for(int kt=0; kt<NKT; kt++){
        if(kt == NKT-1) cpa_wait<0>(); else cpa_wait<1>();
        __syncthreads();
        const uint32_t base = (uint32_t)((kt % 3)*STG_SZ);

        #pragma unroll
        for(int ks=0; ks<4; ks++){
            uint32_t a[4][4];
            #pragma unroll
            for(int im=0; im<4; im++)
                ldsm4(a[im], sbase + (base + aoff[im] + ks*8)*4);
            #pragma unroll
            for(int p=0; p<2; p++){
                uint32_t bf[4];
                ldsm4(bf, sbase + (base + boff[p] + ks*8)*4);
                #pragma unroll
                for(int im=0; im<4; im++){
                    mma_tf32(acc[im][2*p  ], a[im], bf[0], bf[1]);
                    mma_tf32(acc[im][2*p+1], a[im], bf[2], bf[3]);
                }
            }
        }
        if(kt+2 < NKT) load_stage(kt+2, (kt+2)%3);
    }

    // ---- epilogue (direct from registers) ----
    int seg = 0;
    float scale = 1.0f;
    float* outp = oQ;
    int n0s = n0;
    if(fused){
        seg  = n0 >> 10;
        n0s  = n0 & 1023;
        outp = (seg==0) ? oQ : (seg==1) ? oK : oV;
        scale = (seg==0) ? 0.125f : 1.0f;
    }
    #pragma unroll
    for(int im=0; im<4; im++){
        #pragma unroll
        for(int jn=0; jn<4; jn++){
            int nc = wn*32 + jn*8 + (lane&3)*2;
            float b0 = bias[n0+nc], b1 = bias[n0+nc+1];
            #pragma unroll
            for(int half=0; half<2; half++){
                int r = m0 + wm*64 + im*16 + (lane>>2) + half*8;
                float v0 = acc[im][jn][half*2+0] + b0;
                float v1 = acc[im][jn][half*2+1] + b1;
                if(fused){
                    v0 = rt(v0*scale);
                    v1 = rt(v1*scale);
                    int bidx = r >> 11;
                    int srow = r & (SEQ-1);
                    int ncol = n0s + nc;
                    int head = ncol >> 6, d = ncol & 63;
                    size_t bh = (size_t)(bidx*HEADS + head);
                    if(seg == 2){
                        outp[(bh*HDIM + d  )*SEQ + srow] = v0;
                        outp[(bh*HDIM + d+1)*SEQ + srow] = v1;
                    }else{
                        *(float2*)&outp[(bh*SEQ + srow)*HDIM + d] = make_float2(v0, v1);
                    }
                }else{
                    *(float2*)&outp[(size_t)r*EMB + n0 + nc] = make_float2(v0, v1);
                }
            }
        }
    }
}

// =============================================================================
// Flash attention (unchanged): 128 threads, FBQ=128, M_warp=32,
// Q register-resident, K/V(P) via ldmatrix, V d-major, tf32 pre-rounded.
// =============================================================================
#define FBQ 128
#define FBK 64
#define KSTR 68
#define VTSTR 68
#define PSTR 68
#define KS_OFF   0
#define KS_STAGE (FBK*KSTR)
#define VS_OFF   (2*KS_STAGE)
#define VS_STAGE (HDIM*VTSTR)
#define QP_OFF   (VS_OFF + 2*VS_STAGE)
#define QP_SZ    (FBQ*PSTR)
#define BI_OFF   (QP_OFF + QP_SZ)
#define FLASH_SMEM_BYTES ((BI_OFF + 128)*4)

__global__ __launch_bounds__(128, 2) void flash_attn(
    const float* __restrict__ Qg_, const float* __restrict__ Kg_,
    const float* __restrict__ Vg_, const int* __restrict__ mask,
    float* __restrict__ ctx)
{
    extern __shared__ float sm[];
    const uint32_t sbase = (uint32_t)__cvta_generic_to_shared(sm);
    const int tid = threadIdx.x, lane = tid&31, w = tid>>5;
    const int bh = blockIdx.y, b = bh>>4, h = bh&15;
    const int q0 = blockIdx.x * FBQ;
    const float* Qg = Qg_ + (size_t)bh*SEQ*HDIM;
    const float* Kg = Kg_ + (size_t)bh*SEQ*HDIM;
    const float* Vg = Vg_ + (size_t)bh*HDIM*SEQ;

    #pragma unroll
    for(int i=0;i<16;i++){
        int idx = tid + i*128;
        int r = idx>>4, c = (idx&15)*4;
        cpa16(sbase + (uint32_t)((QP_OFF + r*PSTR + c)*4),
              Qg + (size_t)(q0+r)*HDIM + c);
    }
    cpa_commit();

    auto loadKV = [&](int kt, int st){
        const int k0 = kt*FBK;
        #pragma unroll
        for(int i=0;i<8;i++){
            int idx = tid + i*128;
            int r = idx>>4, c = (idx&15)*4;
            cpa16(sbase + (uint32_t)((KS_OFF + st*KS_STAGE + r*KSTR + c)*4),
                  Kg + (size_t)(k0+r)*HDIM + c);
        }
        #pragma unroll
        for(int i=0;i<8;i++){
            int idx = tid + i*128;
            int r = idx>>4, c = (idx&15)*4;
            cpa16(sbase + (uint32_t)((VS_OFF + st*VS_STAGE + r*VTSTR + c)*4),
                  Vg + (size_t)r*SEQ + k0 + c);
        }
        if(tid < FBK){
            int mv = mask[b*SEQ + k0 + tid];
            sm[BI_OFF + st*FBK + tid] = mv ? 0.0f : -1e9f;
        }
        cpa_commit();
    };
    loadKV(0, 0);

    cpa_wait<1>();
    __syncthreads();

    const int bm = lane >> 3, br = lane & 7;
    uint32_t koff[4], voff[4], poff[2];
    #pragma unroll
    for(int p=0; p<4; p++){
        int n = (2*p + (bm>>1))*8 + br;
        koff[p] = (uint32_t)(n*KSTR  + (bm&1)*4);
        voff[p] = (uint32_t)(n*VTSTR + (bm&1)*4);
    }
    #pragma unroll
    for(int im=0; im<2; im++){
        int r = w*32 + im*16 + (lane&7) + ((lane>>3)&1)*8;
        poff[im] = (uint32_t)(QP_OFF + r*PSTR + (lane>>4)*4);
    }

    uint32_t qf[8][2][4];
    #pragma unroll
    for(int kd=0; kd<8; kd++){
        #pragma unroll
        for(int im=0; im<2; im++)
            ldsm4(qf[kd][im], sbase + (poff[im] + kd*8)*4);
    }

    float m_[2][2] = {{-1e30f,-1e30f},{-1e30f,-1e30f}};
    float l_[2][2] = {{0.f,0.f},{0.f,0.f}};
    float o[2][8][4] = {};

    const int NT = SEQ/FBK;
    for(int kt=0; kt<NT; kt++){
        if(kt+1 < NT){ loadKV(kt+1, (kt+1)&1); cpa_wait<1>(); }
        else         { cpa_wait<0>(); }
        __syncthreads();
        const int st = kt & 1;
        const uint32_t kb = (uint32_t)(KS_OFF + st*KS_STAGE);
        const uint32_t vb = (uint32_t)(VS_OFF + st*VS_STAGE);

        float s[2][8][4] = {};
        #pragma unroll
        for(int kd=0; kd<8; kd++){
            #pragma unroll
            for(int p=0; p<4; p++){
                uint32_t kf[4];
                ldsm4(kf, sbase + (kb + koff[p] + kd*8)*4);
                mma_tf32(s[0][2*p  ], qf[kd][0], kf[0], kf[1]);
                mma_tf32(s[1][2*p  ], qf[kd][1], kf[0], kf[1]);
                mma_tf32(s[0][2*p+1], qf[kd][0], kf[2], kf[3]);
                mma_tf32(s[1][2*p+1], qf[kd][1], kf[2], kf[3]);
            }
        }

        #pragma unroll
        for(int im=0; im<2; im++){
            float tm0 = -1e30f, tm1 = -1e30f;
            #pragma unroll
            for(int jn=0; jn<8; jn++){
                int col = jn*8 + (lane&3)*2;
                float bb0 = sm[BI_OFF + st*FBK + col];
                float bb1 = sm[BI_OFF + st*FBK + col+1];
                s[im][jn][0] += bb0; tm0 = fmaxf(tm0, s[im][jn][0]);
                s[im][jn][1] += bb1; tm0 = fmaxf(tm0, s[im][jn][1]);
                s[im][jn][2] += bb0; tm1 = fmaxf(tm1, s[im][jn][2]);
                s[im][jn][3] += bb1; tm1 = fmaxf(tm1, s[im][jn][3]);
            }
            tm0 = fmaxf(tm0, __shfl_xor_sync(0xffffffffu, tm0, 1));
            tm0 = fmaxf(tm0, __shfl_xor_sync(0xffffffffu, tm0, 2));
            tm1 = fmaxf(tm1, __shfl_xor_sync(0xffffffffu, tm1, 1));
            tm1 = fmaxf(tm1, __shfl_xor_sync(0xffffffffu, tm1, 2));
            float mn0 = fmaxf(m_[im][0], tm0), mn1 = fmaxf(m_[im][1], tm1);
            float al0 = __expf(m_[im][0]-mn0), al1 = __expf(m_[im][1]-mn1);
            m_[im][0] = mn0; m_[im][1] = mn1;
            float rs0 = 0.f, rs1 = 0.f;
            #pragma unroll
            for(int jn=0; jn<8; jn++){
                s[im][jn][0] = __expf(s[im][jn][0]-mn0); rs0 += s[im][jn][0];
                s[im][jn][1] = __expf(s[im][jn][1]-mn0); rs0 += s[im][jn][1];
                s[im][jn][2] = __expf(s[im][jn][2]-mn1); rs1 += s[im][jn][2];
                s[im][jn][3] = __expf(s[im][jn][3]-mn1); rs1 += s[im][jn][3];
            }
            rs0 += __shfl_xor_sync(0xffffffffu, rs0, 1);
            rs0 += __shfl_xor_sync(0xffffffffu, rs0, 2);
            rs1 += __shfl_xor_sync(0xffffffffu, rs1, 1);
            rs1 += __shfl_xor_sync(0xffffffffu, rs1, 2);
            l_[im][0] = l_[im][0]*al0 + rs0;
            l_[im][1] = l_[im][1]*al1 + rs1;
            #pragma unroll
            for(int jd=0; jd<8; jd++){
                o[im][jd][0]*=al0; o[im][jd][1]*=al0;
                o[im][jd][2]*=al1; o[im][jd][3]*=al1;
            }
        }

        #pragma unroll
        for(int im=0; im<2; im++){
            int pr = w*32 + im*16 + (lane>>2);
            #pragma unroll
            for(int jn=0; jn<8; jn++){
                int cc = jn*8 + (lane&3)*2;
                *(float2*)&sm[QP_OFF + pr*PSTR + cc] = make_float2(
                    rt(s[im][jn][0]), rt(s[im][jn][1]));
                *(float2*)&sm[QP_OFF + (pr+8)*PSTR + cc] = make_float2(
                    rt(s[im][jn][2]), rt(s[im][jn][3]));
            }
        }
        __syncwarp();

        #pragma unroll
        for(int kk=0; kk<8; kk++){
            uint32_t pf[2][4];
            ldsm4(pf[0], sbase + (poff[0] + kk*8)*4);
            ldsm4(pf[1], sbase + (poff[1] + kk*8)*4);
            #pragma unroll
            for(int p=0; p<4; p++){
                uint32_t vf[4];
                ldsm4(vf, sbase + (vb + voff[p] + kk*8)*4);
                mma_tf32(o[0][2*p  ], pf[0], vf[0], vf[1]);
                mma_tf32(o[1][2*p  ], pf[1], vf[0], vf[1]);
                mma_tf32(o[0][2*p+1], pf[0], vf[2], vf[3]);
                mma_tf32(o[1][2*p+1], pf[1], vf[2], vf[3]);
            }
        }
        __syncthreads();
    }

    #pragma unroll
    for(int im=0; im<2; im++){
        float inv0 = 1.0f/l_[im][0], inv1 = 1.0f/l_[im][1];
        int gr0 = q0 + w*32 + im*16 + (lane>>2);
        #pragma unroll
        for(int jd=0; jd<8; jd++){
            int col = h*HDIM + jd*8 + (lane&3)*2;
            *(float2*)&ctx[(size_t)(b*SEQ + gr0  )*EMB + col] = make_float2(
                rt(o[im][jd][0]*inv0), rt(o[im][jd][1]*inv0));
            *(float2*)&ctx[(size_t)(b*SEQ + gr0+8)*EMB + col] = make_float2(
                rt(o[im][jd][2]*inv1), rt(o[im][jd][3]*inv1));
        }
    }
}

// =============================================================================
extern "C" void kernel_launch(void* const* d_in, const int* in_sizes, int n_in,
                              void* d_out, int out_size)
{
    const float* x    = (const float*)d_in[0];
    const int*   mask = (const int*)  d_in[1];
    const float* Wq   = (const float*)d_in[2];
    const float* bq   = (const float*)d_in[3];
    const float* Wk   = (const float*)d_in[4];
    const float* bk   = (const float*)d_in[5];
    const float* Wv   = (const float*)d_in[6];
    const float* bv   = (const float*)d_in[7];
    const float* Wo   = (const float*)d_in[8];
    const float* bo   = (const float*)d_in[9];
    float* out = (float*)d_out;

    float *qp, *kp, *vp, *cp, *xp, *wp, *bp;
    cudaGetSymbolAddress((void**)&qp, g_q);
    cudaGetSymbolAddress((void**)&kp, g_k);
    cudaGetSymbolAddress((void**)&vp, g_v);
    cudaGetSymbolAddress((void**)&cp, g_ctx);
    cudaGetSymbolAddress((void**)&xp, g_x);
    cudaGetSymbolAddress((void**)&wp, g_w);
    cudaGetSymbolAddress((void**)&bp, g_b);

    cudaFuncSetAttribute(gemm_nt,   cudaFuncAttributeMaxDynamicSharedMemorySize, GEMM_SMEM_BYTES);
    cudaFuncSetAttribute(flash_attn,cudaFuncAttributeMaxDynamicSharedMemorySize, FLASH_SMEM_BYTES);

    // 1) fused prep
    prep_k<<<(PREP_TOTAL+255)/256, 256>>>(
        (const float4*)x, (const float4*)Wq, (const float4*)Wk,
        (const float4*)Wv, (const float4*)Wo,
        bq, bk, bv,
        (float4*)xp, (float4*)wp, bp);

    // 2) fused QKV projection (N=3072)
    dim3 gqkv(3*EMB/GBN, MTOT/GBM);  // (24, 64)
    gemm_nt<<<gqkv, 256, GEMM_SMEM_BYTES>>>(xp, wp, bp, qp, kp, vp, 1);

    // 3) flash attention
    dim3 fg(SEQ/FBQ, BATCH*HEADS);   // (16, 64)
    flash_attn<<<fg, 128, FLASH_SMEM_BYTES>>>(qp, kp, vp, mask, cp);

    // 4) output projection
    dim3 go(EMB/GBN, MTOT/GBM);      // (8, 64)
    gemm_nt<<<go, 256, GEMM_SMEM_BYTES>>>(cp, wp+3*(size_t)EMB*EMB, bo, out, nullptr, nullptr, 0);
}

// round 11
// speedup vs baseline: 2.1676x; 1.6983x over previous
#include <cuda_runtime.h>
#include <cuda_fp16.h>
#include <cstdint>

#define BATCH 4
#define SEQ   2048
#define EMB   1024
#define HEADS 16
#define HDIM  64
#define MTOT  (BATCH*SEQ)   // 8192

// ---------------- scratch (device globals: allocation-free rule) -------------
__device__ __half g_q[MTOT*EMB];      // fp16, pre-scaled 1/8, [bh][s][d]
__device__ __half g_k[MTOT*EMB];      // fp16, [bh][s][d]
__device__ __half g_v[MTOT*EMB];      // fp16, TRANSPOSED [bh][d][s]
__device__ __half g_ctx[MTOT*EMB];    // fp16, [B,S,E]
__device__ __half g_x[MTOT*EMB];      // fp16 input
__device__ __half g_w[4*EMB*EMB];     // fp16 Wq,Wk,Wv,Wo (contiguous)
__device__ float  g_b[3*EMB];         // packed bq|bk|bv (f32)

// ---------------- PTX helpers ------------------------------------------------
__device__ __forceinline__ uint32_t pack_h2(float lo, float hi){
    __half2 h = __floats2half2_rn(lo, hi);
    return *(uint32_t*)&h;
}
__device__ __forceinline__ void ldsm4(uint32_t a[4], uint32_t saddr){
    asm volatile("ldmatrix.sync.aligned.m8n8.x4.shared.b16 {%0,%1,%2,%3}, [%4];"
        : "=r"(a[0]),"=r"(a[1]),"=r"(a[2]),"=r"(a[3]) : "r"(saddr));
}
__device__ __forceinline__ void mma_f16(float c[4], const uint32_t a[4],
                                        uint32_t b0, uint32_t b1){
    asm volatile(
        "mma.sync.aligned.m16n8k16.row.col.f32.f16.f16.f32 "
        "{%0,%1,%2,%3},{%4,%5,%6,%7},{%8,%9},{%0,%1,%2,%3};"
        : "+f"(c[0]),"+f"(c[1]),"+f"(c[2]),"+f"(c[3])
        : "r"(a[0]),"r"(a[1]),"r"(a[2]),"r"(a[3]),"r"(b0),"r"(b1));
}
__device__ __forceinline__ void cpa16(uint32_t dst, const void* src){
    asm volatile("cp.async.ca.shared.global [%0], [%1], 16;\n" :: "r"(dst), "l"(src));
}
__device__ __forceinline__ void cpa_commit(){ asm volatile("cp.async.commit_group;\n"); }
template<int N> __device__ __forceinline__ void cpa_wait(){
    asm volatile("cp.async.wait_group %0;\n" :: "n"(N));
}

// ---------------- fused prep: f32 -> fp16 x + 4 W, pack biases ---------------
#define N4X (MTOT*EMB/4)     // 2097152
#define N4W (EMB*EMB/4)      // 262144
__device__ __forceinline__ uint2 h4(float4 v){
    uint2 r; r.x = pack_h2(v.x, v.y); r.y = pack_h2(v.z, v.w); return r;
}
__global__ void prep_k(
    const float4* __restrict__ x,
    const float4* __restrict__ Wq, const float4* __restrict__ Wk,
    const float4* __restrict__ Wv, const float4* __restrict__ Wo,
    const float*  __restrict__ bq, const float* __restrict__ bk,
    const float*  __restrict__ bv,
    uint2* __restrict__ xp, uint2* __restrict__ wp, float* __restrict__ bp)
{
    int i = blockIdx.x*blockDim.x + threadIdx.x;
    if(i < N4X){
        xp[i] = h4(x[i]);
    } else if(i < N4X + 4*N4W){
        int j = i - N4X;
        int w = j >> 18;
        int off = j & (N4W-1);
        const float4* src = (w==0)?Wq : (w==1)?Wk : (w==2)?Wv : Wo;
        wp[(size_t)w*N4W + off] = h4(src[off]);
    } else {
        int j = i - (N4X + 4*N4W);
        if(j < 3*EMB){
            int seg = j >> 10, off = j & (EMB-1);
            const float* src = (seg==0)?bq : (seg==1)?bk : bv;
            bp[j] = src[off];
        }
    }
}
#define PREP_TOTAL (N4X + 4*N4W + 3*EMB)

// =============================================================================
// fp16 NT GEMM: 128x128 block, 8 warps (2x4), warp tile 64x32, m16n8k16.
// 3-stage cp.async; padded stride 40 fp16 (80B = 5x16B -> conflict-free ldsm).
// fused=1: N=3072 (Wq|Wk|Wv); Q scaled 1/8; V stored transposed [bh][d][s].
// fused=0: flat f32 [M,1024] store.
// =============================================================================
#define GBM 128
#define GBN 128
#define GBK 32
#define ASTRH 40                          // fp16 units
#define A_STG_H (GBM*ASTRH)               // 5120
#define B_STG_H (GBN*ASTRH)               // 5120
#define STG_H   (A_STG_H + B_STG_H)       // 10240
#define GEMM_SMEM_BYTES (3*STG_H*2)       // 61440

__global__ __launch_bounds__(256, 2) void gemm_nt(
    const __half* __restrict__ A, const __half* __restrict__ W,
    const float* __restrict__ bias,
    __half* __restrict__ oQ, __half* __restrict__ oK, __half* __restrict__ oV,
    float* __restrict__ oF, int fused)
{
    extern __shared__ __half smh[];
    const int tid  = threadIdx.x;
    const int lane = tid & 31;
    const int wid  = tid >> 5;
    const int wm   = wid & 1, wn = wid >> 1;   // 2 (M) x 4 (N)
    const int m0 = blockIdx.y * GBM;
    const int n0 = blockIdx.x * GBN;
    const uint32_t sbase = (uint32_t)__cvta_generic_to_shared(smh);

    auto load_stage = [&](int kt, int st){
        const int k0 = kt*GBK;
        const int baseh = st*STG_H;
        const __half* ag = A + (size_t)m0*EMB + k0;
        #pragma unroll
        for(int i=0;i<2;i++){
            int idx = tid + i*256;
            int r = idx>>2, c16 = idx&3;
            cpa16(sbase + (uint32_t)(2*(baseh + r*ASTRH + c16*8)),
                  ag + (size_t)r*EMB + c16*8);
        }
        const __half* wg = W + (size_t)n0*EMB + k0;
        #pragma unroll
        for(int i=0;i<2;i++){
            int idx = tid + i*256;
            int r = idx>>2, c16 = idx&3;
            cpa16(sbase + (uint32_t)(2*(baseh + A_STG_H + r*ASTRH + c16*8)),
                  wg + (size_t)r*EMB + c16*8);
        }
        cpa_commit();
    };

    // ldmatrix lane offsets (fp16 units)
    const int q8 = lane >> 3, lr = lane & 7;
    uint32_t aoff[4], boff[2];
    #pragma unroll
    for(int im=0; im<4; im++)
        aoff[im] = (uint32_t)((wm*64 + im*16 + (lane&15))*ASTRH + (lane>>4)*8);
    #pragma unroll
    for(int p=0; p<2; p++)
        boff[p] = (uint32_t)(A_STG_H +
                   (wn*32 + p*16 + (q8>>1)*8 + lr)*ASTRH + (q8&1)*8);

    float acc[4][4][4] = {};

    load_stage(0, 0);
    load_stage(1, 1);
    const int NKT = EMB/GBK;   // 32
    for(int kt=0; kt<NKT; kt++){
        if(kt == NKT-1) cpa_wait<0>(); else cpa_wait<1>();
        __syncthreads();
        const uint32_t baseh = (uint32_t)((kt % 3)*STG_H);

        #pragma unroll
        for(int ks=0; ks<2; ks++){            // two k16 steps per K=32 chunk
            uint32_t a[4][4];
            #pragma unroll
            for(int im=0; im<4; im++)
                ldsm4(a[im], sbase + 2*(baseh + aoff[im] + ks*16));
            #pragma unroll
            for(int p=0; p<2; p++){
                uint32_t bf[4];
                ldsm4(bf, sbase + 2*(baseh + boff[p] + ks*16));
                #pragma unroll
                for(int im=0; im<4; im++){
                    mma_f16(acc[im][2*p  ], a[im], bf[0], bf[1]);
                    mma_f16(acc[im][2*p+1], a[im], bf[2], bf[3]);
                }
            }
        }
        if(kt+2 < NKT) load_stage(kt+2, (kt+2)%3);
    }

    // ---- epilogue ----
    int seg = 0;
    float scale = 1.0f;
    __half* outp = oQ;
    int n0s = n0;
    if(fused){
        seg  = n0 >> 10;
        n0s  = n0 & 1023;
        outp = (seg==0) ? oQ : (seg==1) ? oK : oV;
        scale = (seg==0) ? 0.125f : 1.0f;
    }
    #pragma unroll
    for(int im=0; im<4; im++){
        #pragma unroll
        for(int jn=0; jn<4; jn++){
            int nc = wn*32 + jn*8 + (lane&3)*2;
            float b0 = bias[n0+nc], b1 = bias[n0+nc+1];
            #pragma unroll
            for(int half_=0; half_<2; half_++){
                int r = m0 + wm*64 + im*16 + (lane>>2) + half_*8;
                float v0 = acc[im][jn][half_*2+0] + b0;
                float v1 = acc[im][jn][half_*2+1] + b1;
                if(fused){
                    int bidx = r >> 11;
                    int srow = r & (SEQ-1);
                    int ncol = n0s + nc;
                    int head = ncol >> 6, d = ncol & 63;
                    size_t bh = (size_t)(bidx*HEADS + head);
                    if(seg == 2){
                        outp[(bh*HDIM + d  )*SEQ + srow] = __float2half_rn(v0);
                        outp[(bh*HDIM + d+1)*SEQ + srow] = __float2half_rn(v1);
                    }else{
                        *(uint32_t*)&outp[(bh*SEQ + srow)*HDIM + d] =
                            pack_h2(v0*scale, v1*scale);
                    }
                }else{
                    *(float2*)&oF[(size_t)r*EMB + n0 + nc] = make_float2(v0, v1);
                }
            }
        }
    }
}

// =============================================================================
// Flash attention fp16: 128 threads (4 warps), FBQ=128, M_warp=32, m16n8k16.
// Q register-resident; K/V/P fp16 in smem, stride 72 (144B = 9x16B, conflict-
// free ldsm); fp32 accumulators + softmax.
// =============================================================================
#define FBQ 128
#define FBK 64
#define KSTRH 72
#define KS_H   0
#define KSTG_H (FBK*KSTRH)                // 4608
#define VS_H   (2*KSTG_H)                 // 9216
#define VSTG_H (HDIM*KSTRH)               // 4608
#define QP_H   (VS_H + 2*VSTG_H)          // 18432
#define QP_SZ_H (FBQ*KSTRH)               // 9216
#define BI_H   (QP_H + QP_SZ_H)           // 27648 halves (byte 55296)
#define FLASH_SMEM_BYTES (BI_H*2 + 2*FBK*4 + 64)   // ~55.9 KB

__global__ __launch_bounds__(128, 2) void flash_attn(
    const __half* __restrict__ Qg_, const __half* __restrict__ Kg_,
    const __half* __restrict__ Vg_, const int* __restrict__ mask,
    __half* __restrict__ ctx)
{
    extern __shared__ __half smh[];
    float* smf = (float*)(smh + BI_H);
    const uint32_t sbase = (uint32_t)__cvta_generic_to_shared(smh);
    const int tid = threadIdx.x, lane = tid&31, w = tid>>5;
    const int bh = blockIdx.y, b = bh>>4, h = bh&15;
    const int q0 = blockIdx.x * FBQ;
    const __half* Qg = Qg_ + (size_t)bh*SEQ*HDIM;
    const __half* Kg = Kg_ + (size_t)bh*SEQ*HDIM;
    const __half* Vg = Vg_ + (size_t)bh*HDIM*SEQ;   // [d][s]

    // Q tile -> smem (group 0): 128 rows x 64 fp16 = 8 chunks/row? (128B/row)
    #pragma unroll
    for(int i=0;i<8;i++){
        int idx = tid + i*128;
        int r = idx>>3, c16 = idx&7;
        cpa16(sbase + (uint32_t)(2*(QP_H + r*KSTRH + c16*8)),
              Qg + (size_t)(q0+r)*HDIM + c16*8);
    }
    cpa_commit();

    auto loadKV = [&](int kt, int st){
        const int k0 = kt*FBK;
        #pragma unroll
        for(int i=0;i<4;i++){
            int idx = tid + i*128;
            int r = idx>>3, c16 = idx&7;
            cpa16(sbase + (uint32_t)(2*(KS_H + st*KSTG_H + r*KSTRH + c16*8)),
                  Kg + (size_t)(k0+r)*HDIM + c16*8);
        }
        #pragma unroll
        for(int i=0;i<4;i++){
            int idx = tid + i*128;
            int r = idx>>3, c16 = idx&7;   // r = d row
            cpa16(sbase + (uint32_t)(2*(VS_H + st*VSTG_H + r*KSTRH + c16*8)),
                  Vg + (size_t)r*SEQ + k0 + c16*8);
        }
        if(tid < FBK){
            int mv = mask[b*SEQ + k0 + tid];
            smf[st*FBK + tid] = mv ? 0.0f : -1e9f;
        }
        cpa_commit();
    };
    loadKV(0, 0);

    cpa_wait<1>();   // Q ready
    __syncthreads();

    // ldmatrix lane offsets (fp16 units)
    const int q8 = lane >> 3, lr = lane & 7;
    uint32_t koff[4], poff[2];
    #pragma unroll
    for(int p=0; p<4; p++)
        koff[p] = (uint32_t)((p*16 + (q8>>1)*8 + lr)*KSTRH + (q8&1)*8);
    #pragma unroll
    for(int im=0; im<2; im++)
        poff[im] = (uint32_t)(QP_H + (w*32 + im*16 + (lane&15))*KSTRH + (lane>>4)*8);

    // Q fragments -> registers (4 k16-steps over d=64)
    uint32_t qf[4][2][4];
    #pragma unroll
    for(int kd=0; kd<4; kd++)
        #pragma unroll
        for(int im=0; im<2; im++)
            ldsm4(qf[kd][im], sbase + 2*(poff[im] + kd*16));

    float m_[2][2] = {{-1e30f,-1e30f},{-1e30f,-1e30f}};
    float l_[2][2] = {{0.f,0.f},{0.f,0.f}};
    float o[2][8][4] = {};

    const int NT = SEQ/FBK;   // 32
    for(int kt=0; kt<NT; kt++){
        if(kt+1 < NT){ loadKV(kt+1, (kt+1)&1); cpa_wait<1>(); }
        else         { cpa_wait<0>(); }
        __syncthreads();
        const int st = kt & 1;
        const uint32_t kb = (uint32_t)(KS_H + st*KSTG_H);
        const uint32_t vb = (uint32_t)(VS_H + st*VSTG_H);

        // ---- S = Q K^T (Q pre-scaled 1/8) ----
        float s[2][8][4] = {};
        #pragma unroll
        for(int kd=0; kd<4; kd++){
            #pragma unroll
            for(int p=0; p<4; p++){
                uint32_t kf[4];
                ldsm4(kf, sbase + 2*(kb + koff[p] + kd*16));
                mma_f16(s[0][2*p  ], qf[kd][0], kf[0], kf[1]);
                mma_f16(s[1][2*p  ], qf[kd][1], kf[0], kf[1]);
                mma_f16(s[0][2*p+1], qf[kd][0], kf[2], kf[3]);
                mma_f16(s[1][2*p+1], qf[kd][1], kf[2], kf[3]);
            }
        }

        // ---- online softmax (unchanged, fp32) ----
        #pragma unroll
        for(int im=0; im<2; im++){
            float tm0 = -1e30f, tm1 = -1e30f;
            #pragma unroll
            for(int jn=0; jn<8; jn++){
                int col = jn*8 + (lane&3)*2;
                float bb0 = smf[st*FBK + col];
                float bb1 = smf[st*FBK + col+1];
                s[im][jn][0] += bb0; tm0 = fmaxf(tm0, s[im][jn][0]);
                s[im][jn][1] += bb1; tm0 = fmaxf(tm0, s[im][jn][1]);
                s[im][jn][2] += bb0; tm1 = fmaxf(tm1, s[im][jn][2]);
                s[im][jn][3] += bb1; tm1 = fmaxf(tm1, s[im][jn][3]);
            }
            tm0 = fmaxf(tm0, __shfl_xor_sync(0xffffffffu, tm0, 1));
            tm0 = fmaxf(tm0, __shfl_xor_sync(0xffffffffu, tm0, 2));
            tm1 = fmaxf(tm1, __shfl_xor_sync(0xffffffffu, tm1, 1));
            tm1 = fmaxf(tm1, __shfl_xor_sync(0xffffffffu, tm1, 2));
            float mn0 = fmaxf(m_[im][0], tm0), mn1 = fmaxf(m_[im][1], tm1);
            float al0 = __expf(m_[im][0]-mn0), al1 = __expf(m_[im][1]-mn1);
            m_[im][0] = mn0; m_[im][1] = mn1;
            float rs0 = 0.f, rs1 = 0.f;
            #pragma unroll
            for(int jn=0; jn<8; jn++){
                s[im][jn][0] = __expf(s[im][jn][0]-mn0); rs0 += s[im][jn][0];
                s[im][jn][1] = __expf(s[im][jn][1]-mn0); rs0 += s[im][jn][1];
                s[im][jn][2] = __expf(s[im][jn][2]-mn1); rs1 += s[im][jn][2];
                s[im][jn][3] = __expf(s[im][jn][3]-mn1); rs1 += s[im][jn][3];
            }
            rs0 += __shfl_xor_sync(0xffffffffu, rs0, 1);
            rs0 += __shfl_xor_sync(0xffffffffu, rs0, 2);
            rs1 += __shfl_xor_sync(0xffffffffu, rs1, 1);
            rs1 += __shfl_xor_sync(0xffffffffu, rs1, 2);
            l_[im][0] = l_[im][0]*al0 + rs0;
            l_[im][1] = l_[im][1]*al1 + rs1;
            #pragma unroll
            for(int jd=0; jd<8; jd++){
                o[im][jd][0]*=al0; o[im][jd][1]*=al0;
                o[im][jd][2]*=al1; o[im][jd][3]*=al1;
            }
        }

        // ---- P (fp16) -> smem, reusing Q region (warp-exclusive rows) ----
        #pragma unroll
        for(int im=0; im<2; im++){
            int pr = w*32 + im*16 + (lane>>2);
            #pragma unroll
            for(int jn=0; jn<8; jn++){
                int cc = jn*8 + (lane&3)*2;
                *(uint32_t*)&smh[QP_H + pr*KSTRH + cc] =
                    pack_h2(s[im][jn][0], s[im][jn][1]);
                *(uint32_t*)&smh[QP_H + (pr+8)*KSTRH + cc] =
                    pack_h2(s[im][jn][2], s[im][jn][3]);
            }
        }
        __syncwarp();

        // ---- O += P V ----
        #pragma unroll
        for(int kk=0; kk<4; kk++){
            uint32_t pf[2][4];
            ldsm4(pf[0], sbase + 2*(poff[0] + kk*16));
            ldsm4(pf[1], sbase + 2*(poff[1] + kk*16));
            #pragma unroll
            for(int p=0; p<4; p++){
                uint32_t vf[4];
                ldsm4(vf, sbase + 2*(vb + koff[p] + kk*16));
                mma_f16(o[0][2*p  ], pf[0], vf[0], vf[1]);
                mma_f16(o[1][2*p  ], pf[1], vf[0], vf[1]);
                mma_f16(o[0][2*p+1], pf[0], vf[2], vf[3]);
                mma_f16(o[1][2*p+1], pf[1], vf[2], vf[3]);
            }
        }
        __syncthreads();
    }

    // epilogue -> ctx fp16 [B,S,E]
    #pragma unroll
    for(int im=0; im<2; im++){
        float inv0 = 1.0f/l_[im][0], inv1 = 1.0f/l_[im][1];
        int gr0 = q0 + w*32 + im*16 + (lane>>2);
        #pragma unroll
        for(int jd=0; jd<8; jd++){
            int col = h*HDIM + jd*8 + (lane&3)*2;
            *(uint32_t*)&ctx[(size_t)(b*SEQ + gr0  )*EMB + col] =
                pack_h2(o[im][jd][0]*inv0, o[im][jd][1]*inv0);
            *(uint32_t*)&ctx[(size_t)(b*SEQ + gr0+8)*EMB + col] =
                pack_h2(o[im][jd][2]*inv1, o[im][jd][3]*inv1);
        }
    }
}

// =============================================================================
extern "C" void kernel_launch(void* const* d_in, const int* in_sizes, int n_in,
                              void* d_out, int out_size)
{
    const float* x    = (const float*)d_in[0];
    const int*   mask = (const int*)  d_in[1];
    const float* Wq   = (const float*)d_in[2];
    const float* bq   = (const float*)d_in[3];
    const float* Wk   = (const float*)d_in[4];
    const float* bk   = (const float*)d_in[5];
    const float* Wv   = (const float*)d_in[6];
    const float* bv   = (const float*)d_in[7];
    const float* Wo   = (const float*)d_in[8];
    const float* bo   = (const float*)d_in[9];
    float* out = (float*)d_out;

    __half *qp, *kp, *vp, *cp, *xp, *wp;
    float *bp;
    cudaGetSymbolAddress((void**)&qp, g_q);
    cudaGetSymbolAddress((void**)&kp, g_k);
    cudaGetSymbolAddress((void**)&vp, g_v);
    cudaGetSymbolAddress((void**)&cp, g_ctx);
    cudaGetSymbolAddress((void**)&xp, g_x);
    cudaGetSymbolAddress((void**)&wp, g_w);
    cudaGetSymbolAddress((void**)&bp, g_b);

    cudaFuncSetAttribute(gemm_nt,   cudaFuncAttributeMaxDynamicSharedMemorySize, GEMM_SMEM_BYTES);
    cudaFuncSetAttribute(flash_attn,cudaFuncAttributeMaxDynamicSharedMemorySize, FLASH_SMEM_BYTES);

    // 1) fused prep (f32 -> fp16)
    prep_k<<<(PREP_TOTAL+255)/256, 256>>>(
        (const float4*)x, (const float4*)Wq, (const float4*)Wk,
        (const float4*)Wv, (const float4*)Wo,
        bq, bk, bv,
        (uint2*)xp, (uint2*)wp, bp);

    // 2) fused QKV projection (N=3072)
    dim3 gqkv(3*EMB/GBN, MTOT/GBM);  // (24, 64)
    gemm_nt<<<gqkv, 256, GEMM_SMEM_BYTES>>>(xp, wp, bp, qp, kp, vp, nullptr, 1);

    // 3) flash attention
    dim3 fg(SEQ/FBQ, BATCH*HEADS);   // (16, 64)
    flash_attn<<<fg, 128, FLASH_SMEM_BYTES>>>(qp, kp, vp, mask, cp);

    // 4) output projection (f32 out)
    dim3 go(EMB/GBN, MTOT/GBM);      // (8, 64)
    gemm_nt<<<go, 256, GEMM_SMEM_BYTES>>>(cp, wp+3*(size_t)EMB*EMB, bo,
                                          nullptr, nullptr, nullptr, out, 0);
}